// round 2
// baseline (speedup 1.0000x reference)
#include <cuda_runtime.h>
#include <cstdint>
#include <cstddef>

#define HEADS 16
#define TSEQ  2048
#define CEMB  1024
#define DH    64
#define BATCH 4
#define BH    (BATCH*HEADS)   // 64
#define BT    (BATCH*TSEQ)    // 8192
#define NT    (TSEQ/64)       // 32 tiles along T
#define NPAIR (NT*(NT+1)/2)   // 528 lower-triangular tile pairs

// ---------------- scratch (device globals; allocation-free) ----------------
__device__ float g_q[(size_t)BH*TSEQ*DH];     // [b,h,t,d] 32MB
__device__ float g_k[(size_t)BH*TSEQ*DH];
__device__ float g_v[(size_t)BH*TSEQ*DH];     // becomes v/Z in-place
__device__ float g_y[(size_t)BT*CEMB];        // concat-head attention out
__device__ float g_Z[(size_t)BH*TSEQ];        // column sums
__device__ float g_Zpart[(size_t)BH*NT*TSEQ]; // per-t-tile partial colsums
__device__ float g_P[(size_t)BH*TSEQ*TSEQ];   // exp(scores), 1 GiB, lower tiles only

// FFMA-only exp: 2^n * poly(r), |t|<=0.347, err ~1.5e-7. Avoids MUFU bottleneck.
__device__ __forceinline__ float fast_exp(float x) {
    x = fmaxf(-60.f, fminf(60.f, x));
    float z = x * 1.4426950408889634f;
    float n = rintf(z);
    float t = (z - n) * 0.6931471805599453f;
    float p = 1.3888889e-3f;
    p = fmaf(p, t, 8.3333333e-3f);
    p = fmaf(p, t, 4.1666667e-2f);
    p = fmaf(p, t, 1.6666667e-1f);
    p = fmaf(p, t, 0.5f);
    p = fmaf(p, t, 1.0f);
    p = fmaf(p, t, 1.0f);
    float s = __int_as_float(((int)n + 127) << 23);
    return p * s;
}

// ---------------- K1: QKV projection -----------------------------------
// grid: (BT/64, 3*HEADS). Per z: X[8192,1024] @ W_h[1024,64] -> [b,h,t,d]
__global__ __launch_bounds__(256) void qkv_kernel(
    const float* __restrict__ x, const float* __restrict__ Wq,
    const float* __restrict__ Wk, const float* __restrict__ Wv)
{
    __shared__ float As[16][64];   // [k][m] transposed
    __shared__ float Bs[16][64];   // [k][n]
    const int tid = threadIdx.x;
    const int m0 = blockIdx.x * 64;
    const int z = blockIdx.y;
    const int which = z >> 4, h = z & 15;
    const float* W = (which == 0) ? Wq : (which == 1) ? Wk : Wv;
    W += (size_t)h * CEMB * DH;
    float* out = (which == 0) ? g_q : (which == 1) ? g_k : g_v;

    const int ty = tid >> 4, tx = tid & 15;
    const int ar = tid >> 2, ac = (tid & 3) * 4;  // A loader: row 0..63, col 0..12
    const int br = tid >> 4, bc = (tid & 15) * 4; // B loader: row 0..15, col 0..60
    float acc[4][4] = {};

    for (int k0 = 0; k0 < CEMB; k0 += 16) {
        float4 av = *(const float4*)&x[(size_t)(m0 + ar) * CEMB + k0 + ac];
        float4 bv = *(const float4*)&W[(size_t)(k0 + br) * DH + bc];
        As[ac + 0][ar] = av.x; As[ac + 1][ar] = av.y;
        As[ac + 2][ar] = av.z; As[ac + 3][ar] = av.w;
        *(float4*)&Bs[br][bc] = bv;
        __syncthreads();
#pragma unroll
        for (int kk = 0; kk < 16; ++kk) {
            float4 a = *(const float4*)&As[kk][ty * 4];
            float4 b = *(const float4*)&Bs[kk][tx * 4];
            float aa[4] = {a.x, a.y, a.z, a.w};
            float bb[4] = {b.x, b.y, b.z, b.w};
#pragma unroll
            for (int i = 0; i < 4; ++i)
#pragma unroll
                for (int j = 0; j < 4; ++j)
                    acc[i][j] = fmaf(aa[i], bb[j], acc[i][j]);
        }
        __syncthreads();
    }
#pragma unroll
    for (int i = 0; i < 4; ++i) {
        int m = m0 + ty * 4 + i;
        int b = m >> 11, t = m & (TSEQ - 1);
        size_t o = (((size_t)(b * HEADS + h) * TSEQ) + t) * DH + tx * 4;
        *(float4*)&out[o] = make_float4(acc[i][0], acc[i][1], acc[i][2], acc[i][3]);
    }
}

// ---------------- K2: scores P=exp(q·k/32), masked; per-tile colsum partials
// grid: (NPAIR, BH). One 64x64 tile per CTA, lower-triangular tiles only.
__global__ __launch_bounds__(256) void scores_kernel()
{
    __shared__ float Qt[64][64];  // [d][t]
    __shared__ float Kt[64][64];  // [d][s]
    __shared__ float red[16][64];
    const int tid = threadIdx.x;
    const int bh = blockIdx.y;
    const int p = blockIdx.x;
    int tt = (int)((sqrtf(8.f * (float)p + 1.f) - 1.f) * 0.5f);
    while ((tt + 1) * (tt + 2) / 2 <= p) ++tt;
    while (tt * (tt + 1) / 2 > p) --tt;
    const int ts = p - tt * (tt + 1) / 2;
    const int t0 = tt * 64, s0 = ts * 64;
    const float* qb = g_q + (size_t)bh * TSEQ * DH;
    const float* kb = g_k + (size_t)bh * TSEQ * DH;

    const int r = tid >> 2;
    const int cb = (tid & 3) * 16;
#pragma unroll
    for (int u = 0; u < 4; ++u) {
        float4 qv = *(const float4*)&qb[(size_t)(t0 + r) * DH + cb + 4 * u];
        float4 kv = *(const float4*)&kb[(size_t)(s0 + r) * DH + cb + 4 * u];
        Qt[cb + 4*u + 0][r] = qv.x; Qt[cb + 4*u + 1][r] = qv.y;
        Qt[cb + 4*u + 2][r] = qv.z; Qt[cb + 4*u + 3][r] = qv.w;
        Kt[cb + 4*u + 0][r] = kv.x; Kt[cb + 4*u + 1][r] = kv.y;
        Kt[cb + 4*u + 2][r] = kv.z; Kt[cb + 4*u + 3][r] = kv.w;
    }
    __syncthreads();

    const int ty = tid >> 4, tx = tid & 15;
    float acc[4][4] = {};
#pragma unroll 8
    for (int d = 0; d < 64; ++d) {
        float4 a = *(const float4*)&Qt[d][ty * 4];
        float4 b = *(const float4*)&Kt[d][tx * 4];
        float aa[4] = {a.x, a.y, a.z, a.w};
        float bb[4] = {b.x, b.y, b.z, b.w};
#pragma unroll
        for (int i = 0; i < 4; ++i)
#pragma unroll
            for (int j = 0; j < 4; ++j)
                acc[i][j] = fmaf(aa[i], bb[j], acc[i][j]);
    }

    const float scale = 0.03125f;  // C^-0.5 = 1/32
    float csum[4] = {0.f, 0.f, 0.f, 0.f};
    float* Prow = g_P + (size_t)bh * TSEQ * TSEQ;
#pragma unroll
    for (int i = 0; i < 4; ++i) {
        const int t = t0 + ty * 4 + i;
        float v4[4];
#pragma unroll
        for (int j = 0; j < 4; ++j) {
            const int s = s0 + tx * 4 + j;
            float e = (s <= t) ? fast_exp(acc[i][j] * scale) : 0.f;
            v4[j] = e;
            csum[j] += e;
        }
        *(float4*)&Prow[(size_t)t * TSEQ + s0 + tx * 4] =
            make_float4(v4[0], v4[1], v4[2], v4[3]);
    }
#pragma unroll
    for (int j = 0; j < 4; ++j) red[ty][tx * 4 + j] = csum[j];
    __syncthreads();
    if (tid < 64) {
        float s = 0.f;
#pragma unroll
        for (int rr = 0; rr < 16; ++rr) s += red[rr][tid];
        g_Zpart[((size_t)bh * NT + tt) * TSEQ + s0 + tid] = s;
    }
}

// ---------------- K3a: reduce partial colsums (fixed order, deterministic)
__global__ void zreduce_kernel()
{
    int idx = blockIdx.x * blockDim.x + threadIdx.x;  // bh*T + s
    if (idx >= BH * TSEQ) return;
    int bh = idx >> 11;
    int s = idx & (TSEQ - 1);
    int ts = s >> 6;
    float sum = 0.f;
    for (int tt = ts; tt < NT; ++tt)
        sum += g_Zpart[((size_t)bh * NT + tt) * TSEQ + s];
    g_Z[idx] = sum;
}

// ---------------- K3b: v[s,:] *= 1/Z[s] in place -----------------------
__global__ void vscale_kernel()
{
    int i4 = blockIdx.x * blockDim.x + threadIdx.x;
    if (i4 >= BH * TSEQ * DH / 4) return;
    float rz = 1.0f / g_Z[i4 >> 4];
    float4* p = (float4*)g_v;
    float4 v = p[i4];
    v.x *= rz; v.y *= rz; v.z *= rz; v.w *= rz;
    p[i4] = v;
}

// ---------------- K4: out_heads = P @ (v/Z), causal tiles only ----------
// grid: (NT, BH). CTA owns 64 query rows; loops s-tiles 0..tt.
__global__ __launch_bounds__(256) void pv_kernel()
{
    __shared__ float Pt[64][64];  // [s][t]
    __shared__ float Vs[64][64];  // [s][d]
    const int tid = threadIdx.x;
    const int tt = blockIdx.x;
    const int bh = blockIdx.y;
    const int t0 = tt * 64;
    const float* Pb = g_P + (size_t)bh * TSEQ * TSEQ;
    const float* vb = g_v + (size_t)bh * TSEQ * DH;
    const int r = tid >> 2;
    const int cb = (tid & 3) * 16;
    const int ty = tid >> 4, tx = tid & 15;
    float acc[4][4] = {};

    for (int st = 0; st <= tt; ++st) {
        const int s0 = st * 64;
#pragma unroll
        for (int u = 0; u < 4; ++u) {
            float4 pv4 = *(const float4*)&Pb[(size_t)(t0 + r) * TSEQ + s0 + cb + 4 * u];
            Pt[cb + 4*u + 0][r] = pv4.x; Pt[cb + 4*u + 1][r] = pv4.y;
            Pt[cb + 4*u + 2][r] = pv4.z; Pt[cb + 4*u + 3][r] = pv4.w;
            float4 vv = *(const float4*)&vb[(size_t)(s0 + r) * DH + cb + 4 * u];
            *(float4*)&Vs[r][cb + 4 * u] = vv;
        }
        __syncthreads();
#pragma unroll 8
        for (int s = 0; s < 64; ++s) {
            float4 a = *(const float4*)&Pt[s][ty * 4];
            float4 b = *(const float4*)&Vs[s][tx * 4];
            float aa[4] = {a.x, a.y, a.z, a.w};
            float bb[4] = {b.x, b.y, b.z, b.w};
#pragma unroll
            for (int i = 0; i < 4; ++i)
#pragma unroll
                for (int j = 0; j < 4; ++j)
                    acc[i][j] = fmaf(aa[i], bb[j], acc[i][j]);
        }
        __syncthreads();
    }
    const int b = bh >> 4, h = bh & 15;
#pragma unroll
    for (int i = 0; i < 4; ++i) {
        const int t = t0 + ty * 4 + i;
        size_t o = ((size_t)(b * TSEQ + t)) * CEMB + h * DH + tx * 4;
        *(float4*)&g_y[o] = make_float4(acc[i][0], acc[i][1], acc[i][2], acc[i][3]);
    }
}

// ---------------- K5: out = y @ Wp^T + bp -------------------------------
// grid: (BT/64, CEMB/64). Both operands K-contiguous -> same transposed-load.
__global__ __launch_bounds__(256) void proj_kernel(
    const float* __restrict__ Wp, const float* __restrict__ bp,
    float* __restrict__ out)
{
    __shared__ float As[16][64];  // [k][m]
    __shared__ float Bs[16][64];  // [k][n]
    const int tid = threadIdx.x;
    const int m0 = blockIdx.x * 64;
    const int n0 = blockIdx.y * 64;
    const int ty = tid >> 4, tx = tid & 15;
    const int ar = tid >> 2, ac = (tid & 3) * 4;
    float acc[4][4] = {};

    for (int k0 = 0; k0 < CEMB; k0 += 16) {
        float4 av = *(const float4*)&g_y[(size_t)(m0 + ar) * CEMB + k0 + ac];
        float4 bv = *(const float4*)&Wp[(size_t)(n0 + ar) * CEMB + k0 + ac];
        As[ac + 0][ar] = av.x; As[ac + 1][ar] = av.y;
        As[ac + 2][ar] = av.z; As[ac + 3][ar] = av.w;
        Bs[ac + 0][ar] = bv.x; Bs[ac + 1][ar] = bv.y;
        Bs[ac + 2][ar] = bv.z; Bs[ac + 3][ar] = bv.w;
        __syncthreads();
#pragma unroll
        for (int kk = 0; kk < 16; ++kk) {
            float4 a = *(const float4*)&As[kk][ty * 4];
            float4 b = *(const float4*)&Bs[kk][tx * 4];
            float aa[4] = {a.x, a.y, a.z, a.w};
            float bb[4] = {b.x, b.y, b.z, b.w};
#pragma unroll
            for (int i = 0; i < 4; ++i)
#pragma unroll
                for (int j = 0; j < 4; ++j)
                    acc[i][j] = fmaf(aa[i], bb[j], acc[i][j]);
        }
        __syncthreads();
    }
    float bias[4];
#pragma unroll
    for (int j = 0; j < 4; ++j) bias[j] = bp[n0 + tx * 4 + j];
#pragma unroll
    for (int i = 0; i < 4; ++i) {
        size_t o = (size_t)(m0 + ty * 4 + i) * CEMB + n0 + tx * 4;
        *(float4*)&out[o] = make_float4(acc[i][0] + bias[0], acc[i][1] + bias[1],
                                        acc[i][2] + bias[2], acc[i][3] + bias[3]);
    }
}

// ---------------- launch -------------------------------------------------
extern "C" void kernel_launch(void* const* d_in, const int* in_sizes, int n_in,
                              void* d_out, int out_size)
{
    const float* x  = (const float*)d_in[0];
    const float* Wq = (const float*)d_in[1];
    const float* Wk = (const float*)d_in[2];
    const float* Wv = (const float*)d_in[3];
    const float* Wp = (const float*)d_in[4];
    const float* bp = (const float*)d_in[5];
    float* out = (float*)d_out;

    qkv_kernel<<<dim3(BT / 64, 3 * HEADS), 256>>>(x, Wq, Wk, Wv);
    scores_kernel<<<dim3(NPAIR, BH), 256>>>();
    zreduce_kernel<<<(BH * TSEQ + 255) / 256, 256>>>();
    vscale_kernel<<<(BH * TSEQ * DH / 4 + 255) / 256, 256>>>();
    pv_kernel<<<dim3(NT, BH), 256>>>();
    proj_kernel<<<dim3(BT / 64, CEMB / 64), 256>>>(Wp, bp, out);
}

// round 3
// speedup vs baseline: 2.4265x; 2.4265x over previous
#include <cuda_runtime.h>
#include <cuda_bf16.h>
#include <cstdint>
#include <cstddef>

#define HEADS 16
#define TSEQ  2048
#define CEMB  1024
#define DH    64
#define BATCH 4
#define BH    (BATCH*HEADS)   // 64
#define BT    (BATCH*TSEQ)    // 8192
#define NT2   16              // 128-row t-tiles
#define APAD  40              // A smem row: 32 k + 8 pad (bf16)
#define BNPAD 40              // natural-B smem row: 32 k + 8 pad
#define BTPAD 72              // trans-B smem row: 64 n + 8 pad

// ---------------- scratch (device globals; allocation-free) ----------------
__device__ __nv_bfloat16 g_qh[(size_t)BH*TSEQ*DH], g_ql[(size_t)BH*TSEQ*DH];
__device__ __nv_bfloat16 g_kh[(size_t)BH*TSEQ*DH], g_kl[(size_t)BH*TSEQ*DH];
__device__ float         g_v [(size_t)BH*TSEQ*DH];
__device__ __nv_bfloat16 g_vh[(size_t)BH*TSEQ*DH], g_vl[(size_t)BH*TSEQ*DH];
__device__ __nv_bfloat16 g_Ph[(size_t)BH*TSEQ*TSEQ];   // 512 MiB
__device__ __nv_bfloat16 g_Pl[(size_t)BH*TSEQ*TSEQ];   // 512 MiB
__device__ __nv_bfloat16 g_yh[(size_t)BT*CEMB], g_yl[(size_t)BT*CEMB];
__device__ float g_Zpart[(size_t)BH*NT2*TSEQ];
__device__ float g_Z[(size_t)BH*TSEQ];

// ---------------- helpers ----------------
__device__ __forceinline__ uint32_t smem_u32(const void* p) {
    return (uint32_t)__cvta_generic_to_shared(p);
}
__device__ __forceinline__ void ldsm4(uint32_t r[4], uint32_t a) {
    asm volatile("ldmatrix.sync.aligned.m8n8.x4.shared.b16 {%0,%1,%2,%3},[%4];"
                 : "=r"(r[0]), "=r"(r[1]), "=r"(r[2]), "=r"(r[3]) : "r"(a));
}
__device__ __forceinline__ void ldsm4t(uint32_t r[4], uint32_t a) {
    asm volatile("ldmatrix.sync.aligned.m8n8.x4.trans.shared.b16 {%0,%1,%2,%3},[%4];"
                 : "=r"(r[0]), "=r"(r[1]), "=r"(r[2]), "=r"(r[3]) : "r"(a));
}
__device__ __forceinline__ void mma16816(float c[4], const uint32_t a[4],
                                         uint32_t b0, uint32_t b1) {
    asm volatile(
        "mma.sync.aligned.m16n8k16.row.col.f32.bf16.bf16.f32 "
        "{%0,%1,%2,%3},{%4,%5,%6,%7},{%8,%9},{%0,%1,%2,%3};"
        : "+f"(c[0]), "+f"(c[1]), "+f"(c[2]), "+f"(c[3])
        : "r"(a[0]), "r"(a[1]), "r"(a[2]), "r"(a[3]), "r"(b0), "r"(b1));
}
__device__ __forceinline__ void split2(float x, __nv_bfloat16& h, __nv_bfloat16& l) {
    h = __float2bfloat16(x);
    l = __float2bfloat16(x - __bfloat162float(h));
}
// store split of (x0,x1) as bf16x2 into hi/lo planes
__device__ __forceinline__ void store_split2(__nv_bfloat16* ph, __nv_bfloat16* pl,
                                             float x0, float x1) {
    __nv_bfloat16 h0, l0, h1, l1;
    split2(x0, h0, l0); split2(x1, h1, l1);
    __nv_bfloat162 hh; hh.x = h0; hh.y = h1;
    __nv_bfloat162 ll; ll.x = l0; ll.y = l1;
    *(__nv_bfloat162*)ph = hh;
    *(__nv_bfloat162*)pl = ll;
}
// convert float4 -> two bf16x2 (hi) + two bf16x2 (lo) into smem rows
__device__ __forceinline__ void smem_split4(__nv_bfloat16* dh, __nv_bfloat16* dl, float4 v) {
    __nv_bfloat16 h0,h1,h2,h3,l0,l1,l2,l3;
    split2(v.x,h0,l0); split2(v.y,h1,l1); split2(v.z,h2,l2); split2(v.w,h3,l3);
    __nv_bfloat162 a; a.x=h0; a.y=h1; __nv_bfloat162 b; b.x=h2; b.y=h3;
    __nv_bfloat162 c; c.x=l0; c.y=l1; __nv_bfloat162 d; d.x=l2; d.y=l3;
    *(__nv_bfloat162*)(dh)   = a; *(__nv_bfloat162*)(dh+2) = b;
    *(__nv_bfloat162*)(dl)   = c; *(__nv_bfloat162*)(dl+2) = d;
}

// FFMA-only exp (no MUFU bottleneck)
__device__ __forceinline__ float fast_exp(float x) {
    x = fmaxf(-60.f, fminf(60.f, x));
    float z = x * 1.4426950408889634f;
    float n = rintf(z);
    float t = (z - n) * 0.6931471805599453f;
    float p = 1.3888889e-3f;
    p = fmaf(p, t, 8.3333333e-3f);
    p = fmaf(p, t, 4.1666667e-2f);
    p = fmaf(p, t, 1.6666667e-1f);
    p = fmaf(p, t, 0.5f);
    p = fmaf(p, t, 1.0f);
    p = fmaf(p, t, 1.0f);
    return p * __int_as_float(((int)n + 127) << 23);
}

// Fragment address helpers (per-warp constants)
struct FragAddr {
    uint32_t aH[2], aL[2];      // A: 2 m16-tiles
    uint32_t bH[2], bL[2];      // B: 2 n16-blocks
};

// ==================== K1: QKV projection ====================
// grid(BT/128, 48). C[8192,64] = X[8192,1024] @ W_h[1024,64]. B via ldsm.trans.
__global__ __launch_bounds__(256) void qkv_kernel(
    const float* __restrict__ x, const float* __restrict__ Wq,
    const float* __restrict__ Wk, const float* __restrict__ Wv)
{
    __shared__ __nv_bfloat16 Ah[128*APAD], Al[128*APAD];
    __shared__ __nv_bfloat16 Bh[32*BTPAD], Bl[32*BTPAD];
    const int tid = threadIdx.x, w = tid >> 5, lane = tid & 31;
    const int wm = w & 3, wn = w >> 2;
    const int m0 = blockIdx.x * 128;
    const int z = blockIdx.y, which = z >> 4, h = z & 15;
    const float* W = ((which == 0) ? Wq : (which == 1) ? Wk : Wv) + (size_t)h * CEMB * DH;

    float acc[2][4][4] = {};
    FragAddr F;
#pragma unroll
    for (int mt = 0; mt < 2; ++mt) {
        int ar = wm*32 + mt*16 + (lane & 15), ak = (lane >> 4) * 8;
        F.aH[mt] = smem_u32(&Ah[ar*APAD + ak]);
        F.aL[mt] = smem_u32(&Al[ar*APAD + ak]);
    }
#pragma unroll
    for (int blk = 0; blk < 2; ++blk) {  // trans-B: row=k, col=n
        int br = (lane & 15), bc = wn*32 + blk*16 + ((lane & 16) ? 8 : 0);
        F.bH[blk] = smem_u32(&Bh[br*BTPAD + bc]);
        F.bL[blk] = smem_u32(&Bl[br*BTPAD + bc]);
    }

    for (int k0 = 0; k0 < CEMB; k0 += 32) {
        // A: 128x32 fp32 -> split planes. 1024 float4 / 256 thr = 4 iters.
#pragma unroll
        for (int i = 0; i < 4; ++i) {
            int idx = tid + i*256, r = idx >> 3, c4 = (idx & 7) * 4;
            float4 v = *(const float4*)&x[(size_t)(m0 + r)*CEMB + k0 + c4];
            smem_split4(&Ah[r*APAD + c4], &Al[r*APAD + c4], v);
        }
        // B: W rows k0..k0+31, 64 cols. 512 float4 / 256 = 2 iters. natural [k][d].
#pragma unroll
        for (int i = 0; i < 2; ++i) {
            int idx = tid + i*256, r = idx >> 4, c4 = (idx & 15) * 4;
            float4 v = *(const float4*)&W[(size_t)(k0 + r)*DH + c4];
            smem_split4(&Bh[r*BTPAD + c4], &Bl[r*BTPAD + c4], v);
        }
        __syncthreads();
#pragma unroll
        for (int k16 = 0; k16 < 2; ++k16) {
            uint32_t aofs = k16 * 32;            // 16 elems * 2B
            uint32_t bofs = k16 * 16 * BTPAD * 2;  // 16 k-rows
            uint32_t ah[2][4], al[2][4], bh[2][4], bl[2][4];
#pragma unroll
            for (int mt = 0; mt < 2; ++mt) { ldsm4(ah[mt], F.aH[mt]+aofs); ldsm4(al[mt], F.aL[mt]+aofs); }
#pragma unroll
            for (int blk = 0; blk < 2; ++blk) { ldsm4t(bh[blk], F.bH[blk]+bofs); ldsm4t(bl[blk], F.bL[blk]+bofs); }
#pragma unroll
            for (int mt = 0; mt < 2; ++mt)
#pragma unroll
                for (int nt = 0; nt < 4; ++nt) {
                    int blk = nt >> 1, p2 = (nt & 1) * 2;
                    mma16816(acc[mt][nt], ah[mt], bh[blk][p2], bh[blk][p2+1]);
                    mma16816(acc[mt][nt], ah[mt], bl[blk][p2], bl[blk][p2+1]);
                    mma16816(acc[mt][nt], al[mt], bh[blk][p2], bh[blk][p2+1]);
                }
        }
        __syncthreads();
    }
    // epilogue
#pragma unroll
    for (int mt = 0; mt < 2; ++mt)
#pragma unroll
        for (int nt = 0; nt < 4; ++nt)
#pragma unroll
            for (int half = 0; half < 2; ++half) {
                int m = m0 + wm*32 + mt*16 + (lane >> 2) + half*8;
                int n = wn*32 + nt*8 + (lane & 3)*2;
                int b = m >> 11, t = m & (TSEQ - 1);
                size_t base = (((size_t)(b*HEADS + h))*TSEQ + t)*DH + n;
                float c0 = acc[mt][nt][half*2], c1 = acc[mt][nt][half*2+1];
                if (which == 2) {
                    *(float2*)&g_v[base] = make_float2(c0, c1);
                } else if (which == 0) {
                    store_split2(&g_qh[base], &g_ql[base], c0, c1);
                } else {
                    store_split2(&g_kh[base], &g_kl[base], c0, c1);
                }
            }
}

// ==================== K2: scores -> P planes + column partials ====================
// grid(272, 64). tile: 128 t-rows x 64 s-cols, lower-triangular tiles only.
__global__ __launch_bounds__(256) void scores_kernel()
{
    __shared__ __nv_bfloat16 Ah[128*APAD], Al[128*APAD];
    __shared__ __nv_bfloat16 Bh[64*BNPAD], Bl[64*BNPAD];
    __shared__ float red[8][32];
    const int tid = threadIdx.x, w = tid >> 5, lane = tid & 31;
    const int wm = w & 3, wn = w >> 2;
    const int bh_ = blockIdx.y;
    int p = blockIdx.x;
    int tt = (int)sqrtf((float)p);
    while (tt*tt + tt > p) --tt;
    while ((tt+1)*(tt+1) + (tt+1) <= p) ++tt;
    const int ss = p - tt*tt - tt;
    const int t0 = tt * 128, s0 = ss * 64;
    const __nv_bfloat16* qh = g_qh + (size_t)bh_*TSEQ*DH;
    const __nv_bfloat16* ql = g_ql + (size_t)bh_*TSEQ*DH;
    const __nv_bfloat16* kh = g_kh + (size_t)bh_*TSEQ*DH;
    const __nv_bfloat16* kl = g_kl + (size_t)bh_*TSEQ*DH;

    float acc[2][4][4] = {};
    FragAddr F;
#pragma unroll
    for (int mt = 0; mt < 2; ++mt) {
        int ar = wm*32 + mt*16 + (lane & 15), ak = (lane >> 4) * 8;
        F.aH[mt] = smem_u32(&Ah[ar*APAD + ak]);
        F.aL[mt] = smem_u32(&Al[ar*APAD + ak]);
    }
#pragma unroll
    for (int blk = 0; blk < 2; ++blk) {  // natural B: row=n(s), col=k(d)
        int br = wn*32 + blk*16 + (lane & 7) + ((lane & 16) ? 8 : 0);
        int bk = (lane & 8) ? 8 : 0;
        F.bH[blk] = smem_u32(&Bh[br*BNPAD + bk]);
        F.bL[blk] = smem_u32(&Bl[br*BNPAD + bk]);
    }

#pragma unroll
    for (int k0 = 0; k0 < DH; k0 += 32) {
        // A: q planes 128x32 bf16: 512 f4/plane -> 2 iters each
#pragma unroll
        for (int i = 0; i < 2; ++i) {
            int idx = tid + i*256, r = idx >> 2, c8 = (idx & 3) * 8;
            *(float4*)&Ah[r*APAD + c8] = *(const float4*)&qh[(size_t)(t0 + r)*DH + k0 + c8];
            *(float4*)&Al[r*APAD + c8] = *(const float4*)&ql[(size_t)(t0 + r)*DH + k0 + c8];
        }
        // B: k planes 64x32 bf16: 256 f4/plane -> 1 iter each
        {
            int idx = tid, r = idx >> 2, c8 = (idx & 3) * 8;
            *(float4*)&Bh[r*BNPAD + c8] = *(const float4*)&kh[(size_t)(s0 + r)*DH + k0 + c8];
            *(float4*)&Bl[r*BNPAD + c8] = *(const float4*)&kl[(size_t)(s0 + r)*DH + k0 + c8];
        }
        __syncthreads();
#pragma unroll
        for (int k16 = 0; k16 < 2; ++k16) {
            uint32_t aofs = k16 * 32, bofs = k16 * 32;
            uint32_t ah[2][4], al[2][4], bhf[2][4], blf[2][4];
#pragma unroll
            for (int mt = 0; mt < 2; ++mt) { ldsm4(ah[mt], F.aH[mt]+aofs); ldsm4(al[mt], F.aL[mt]+aofs); }
#pragma unroll
            for (int blk = 0; blk < 2; ++blk) { ldsm4(bhf[blk], F.bH[blk]+bofs); ldsm4(blf[blk], F.bL[blk]+bofs); }
#pragma unroll
            for (int mt = 0; mt < 2; ++mt)
#pragma unroll
                for (int nt = 0; nt < 4; ++nt) {
                    int blk = nt >> 1, p2 = (nt & 1) * 2;
                    mma16816(acc[mt][nt], ah[mt], bhf[blk][p2], bhf[blk][p2+1]);
                    mma16816(acc[mt][nt], ah[mt], blf[blk][p2], blf[blk][p2+1]);
                    mma16816(acc[mt][nt], al[mt], bhf[blk][p2], bhf[blk][p2+1]);
                }
        }
        __syncthreads();
    }
    // epilogue: exp, P planes, column partials
    const float scale = 0.03125f;
    float cs[4][2] = {};
    size_t Pbase = (size_t)bh_ * TSEQ * TSEQ;
#pragma unroll
    for (int mt = 0; mt < 2; ++mt)
#pragma unroll
        for (int nt = 0; nt < 4; ++nt)
#pragma unroll
            for (int half = 0; half < 2; ++half) {
                int t = t0 + wm*32 + mt*16 + (lane >> 2) + half*8;
                int s = s0 + wn*32 + nt*8 + (lane & 3)*2;
                float e0 = (s     <= t) ? fast_exp(acc[mt][nt][half*2]   * scale) : 0.f;
                float e1 = (s + 1 <= t) ? fast_exp(acc[mt][nt][half*2+1] * scale) : 0.f;
                cs[nt][0] += e0; cs[nt][1] += e1;
                size_t o = Pbase + (size_t)t*TSEQ + s;
                store_split2(&g_Ph[o], &g_Pl[o], e0, e1);
            }
#pragma unroll
    for (int nt = 0; nt < 4; ++nt)
#pragma unroll
        for (int par = 0; par < 2; ++par) {
            float v = cs[nt][par];
            v += __shfl_xor_sync(0xffffffffu, v, 4);
            v += __shfl_xor_sync(0xffffffffu, v, 8);
            v += __shfl_xor_sync(0xffffffffu, v, 16);
            if (lane < 4) red[w][nt*8 + (lane & 3)*2 + par] = v;
        }
    __syncthreads();
    if (tid < 64) {
        int col = tid, wh = col >> 5;
        float s = red[wh*4+0][col & 31] + red[wh*4+1][col & 31]
                + red[wh*4+2][col & 31] + red[wh*4+3][col & 31];
        g_Zpart[((size_t)bh_*NT2 + tt)*TSEQ + s0 + col] = s;
    }
}

// ==================== K3a: Z reduce (deterministic) ====================
__global__ void zreduce_kernel()
{
    int idx = blockIdx.x * blockDim.x + threadIdx.x;
    if (idx >= BH * TSEQ) return;
    int bh_ = idx >> 11, s = idx & (TSEQ - 1), ttmin = s >> 7;
    float sum = 0.f;
    for (int tt = ttmin; tt < NT2; ++tt)
        sum += g_Zpart[((size_t)bh_*NT2 + tt)*TSEQ + s];
    g_Z[idx] = sum;
}

// ==================== K3b: v/Z -> split planes ====================
__global__ void vscale_kernel()
{
    int i4 = blockIdx.x * blockDim.x + threadIdx.x;
    if (i4 >= BH * TSEQ * DH / 4) return;
    float rz = 1.0f / g_Z[i4 >> 4];
    float4 v = ((const float4*)g_v)[i4];
    size_t base = (size_t)i4 * 4;
    store_split2(&g_vh[base],   &g_vl[base],   v.x * rz, v.y * rz);
    store_split2(&g_vh[base+2], &g_vl[base+2], v.z * rz, v.w * rz);
}

// ==================== K4: y = P @ (v/Z) ====================
// grid(16, 64). CTA: 128 t-rows x 64 d. k over s in steps of 32.
__global__ __launch_bounds__(256) void pv_kernel()
{
    __shared__ __nv_bfloat16 Ah[128*APAD], Al[128*APAD];
    __shared__ __nv_bfloat16 Bh[32*BTPAD], Bl[32*BTPAD];
    const int tid = threadIdx.x, w = tid >> 5, lane = tid & 31;
    const int wm = w & 3, wn = w >> 2;
    const int tt = 15 - blockIdx.x;          // big tiles first
    const int bh_ = blockIdx.y;
    const int t0 = tt * 128;
    const __nv_bfloat16* Ph = g_Ph + (size_t)bh_*TSEQ*TSEQ;
    const __nv_bfloat16* Pl = g_Pl + (size_t)bh_*TSEQ*TSEQ;
    const __nv_bfloat16* vh = g_vh + (size_t)bh_*TSEQ*DH;
    const __nv_bfloat16* vl = g_vl + (size_t)bh_*TSEQ*DH;

    float acc[2][4][4] = {};
    FragAddr F;
#pragma unroll
    for (int mt = 0; mt < 2; ++mt) {
        int ar = wm*32 + mt*16 + (lane & 15), ak = (lane >> 4) * 8;
        F.aH[mt] = smem_u32(&Ah[ar*APAD + ak]);
        F.aL[mt] = smem_u32(&Al[ar*APAD + ak]);
    }
#pragma unroll
    for (int blk = 0; blk < 2; ++blk) {  // trans-B: row=k(s), col=n(d)
        int br = (lane & 15), bc = wn*32 + blk*16 + ((lane & 16) ? 8 : 0);
        F.bH[blk] = smem_u32(&Bh[br*BTPAD + bc]);
        F.bL[blk] = smem_u32(&Bl[br*BTPAD + bc]);
    }

    const int nsteps = 4 * (tt + 1);
    for (int st = 0; st < nsteps; ++st) {
        const int s0 = st * 32;
#pragma unroll
        for (int i = 0; i < 2; ++i) {
            int idx = tid + i*256, r = idx >> 2, c8 = (idx & 3) * 8;
            *(float4*)&Ah[r*APAD + c8] = *(const float4*)&Ph[(size_t)(t0 + r)*TSEQ + s0 + c8];
            *(float4*)&Al[r*APAD + c8] = *(const float4*)&Pl[(size_t)(t0 + r)*TSEQ + s0 + c8];
        }
        {   // v planes 32x64: 256 f4/plane -> 1 iter each
            int idx = tid, r = idx >> 3, c8 = (idx & 7) * 8;
            *(float4*)&Bh[r*BTPAD + c8] = *(const float4*)&vh[(size_t)(s0 + r)*DH + c8];
            *(float4*)&Bl[r*BTPAD + c8] = *(const float4*)&vl[(size_t)(s0 + r)*DH + c8];
        }
        __syncthreads();
#pragma unroll
        for (int k16 = 0; k16 < 2; ++k16) {
            uint32_t aofs = k16 * 32, bofs = k16 * 16 * BTPAD * 2;
            uint32_t ah[2][4], al[2][4], bhf[2][4], blf[2][4];
#pragma unroll
            for (int mt = 0; mt < 2; ++mt) { ldsm4(ah[mt], F.aH[mt]+aofs); ldsm4(al[mt], F.aL[mt]+aofs); }
#pragma unroll
            for (int blk = 0; blk < 2; ++blk) { ldsm4t(bhf[blk], F.bH[blk]+bofs); ldsm4t(blf[blk], F.bL[blk]+bofs); }
#pragma unroll
            for (int mt = 0; mt < 2; ++mt)
#pragma unroll
                for (int nt = 0; nt < 4; ++nt) {
                    int blk = nt >> 1, p2 = (nt & 1) * 2;
                    mma16816(acc[mt][nt], ah[mt], bhf[blk][p2], bhf[blk][p2+1]);
                    mma16816(acc[mt][nt], ah[mt], blf[blk][p2], blf[blk][p2+1]);
                    mma16816(acc[mt][nt], al[mt], bhf[blk][p2], bhf[blk][p2+1]);
                }
        }
        __syncthreads();
    }
    // epilogue -> y planes (concat heads)
    const int b = bh_ >> 4, h = bh_ & 15;
#pragma unroll
    for (int mt = 0; mt < 2; ++mt)
#pragma unroll
        for (int nt = 0; nt < 4; ++nt)
#pragma unroll
            for (int half = 0; half < 2; ++half) {
                int t = t0 + wm*32 + mt*16 + (lane >> 2) + half*8;
                int n = wn*32 + nt*8 + (lane & 3)*2;
                size_t o = ((size_t)(b*TSEQ + t))*CEMB + h*DH + n;
                store_split2(&g_yh[o], &g_yl[o],
                             acc[mt][nt][half*2], acc[mt][nt][half*2+1]);
            }
}

// ==================== K5: out = y @ Wp^T + bp ====================
// grid(BT/128, CEMB/64). B natural: Wp [cout][c], n=cout, k=c.
__global__ __launch_bounds__(256) void proj_kernel(
    const float* __restrict__ Wp, const float* __restrict__ bp,
    float* __restrict__ out)
{
    __shared__ __nv_bfloat16 Ah[128*APAD], Al[128*APAD];
    __shared__ __nv_bfloat16 Bh[64*BNPAD], Bl[64*BNPAD];
    const int tid = threadIdx.x, w = tid >> 5, lane = tid & 31;
    const int wm = w & 3, wn = w >> 2;
    const int m0 = blockIdx.x * 128, n0 = blockIdx.y * 64;

    float acc[2][4][4] = {};
    FragAddr F;
#pragma unroll
    for (int mt = 0; mt < 2; ++mt) {
        int ar = wm*32 + mt*16 + (lane & 15), ak = (lane >> 4) * 8;
        F.aH[mt] = smem_u32(&Ah[ar*APAD + ak]);
        F.aL[mt] = smem_u32(&Al[ar*APAD + ak]);
    }
#pragma unroll
    for (int blk = 0; blk < 2; ++blk) {
        int br = wn*32 + blk*16 + (lane & 7) + ((lane & 16) ? 8 : 0);
        int bk = (lane & 8) ? 8 : 0;
        F.bH[blk] = smem_u32(&Bh[br*BNPAD + bk]);
        F.bL[blk] = smem_u32(&Bl[br*BNPAD + bk]);
    }

    for (int k0 = 0; k0 < CEMB; k0 += 32) {
        // A from y planes
#pragma unroll
        for (int i = 0; i < 2; ++i) {
            int idx = tid + i*256, r = idx >> 2, c8 = (idx & 3) * 8;
            *(float4*)&Ah[r*APAD + c8] = *(const float4*)&g_yh[(size_t)(m0 + r)*CEMB + k0 + c8];
            *(float4*)&Al[r*APAD + c8] = *(const float4*)&g_yl[(size_t)(m0 + r)*CEMB + k0 + c8];
        }
        // B from Wp fp32: 64x32 -> 512 f4 -> 2 iters
#pragma unroll
        for (int i = 0; i < 2; ++i) {
            int idx = tid + i*256, r = idx >> 3, c4 = (idx & 7) * 4;
            float4 v = *(const float4*)&Wp[(size_t)(n0 + r)*CEMB + k0 + c4];
            smem_split4(&Bh[r*BNPAD + c4], &Bl[r*BNPAD + c4], v);
        }
        __syncthreads();
#pragma unroll
        for (int k16 = 0; k16 < 2; ++k16) {
            uint32_t aofs = k16 * 32, bofs = k16 * 32;
            uint32_t ah[2][4], al[2][4], bhf[2][4], blf[2][4];
#pragma unroll
            for (int mt = 0; mt < 2; ++mt) { ldsm4(ah[mt], F.aH[mt]+aofs); ldsm4(al[mt], F.aL[mt]+aofs); }
#pragma unroll
            for (int blk = 0; blk < 2; ++blk) { ldsm4(bhf[blk], F.bH[blk]+bofs); ldsm4(blf[blk], F.bL[blk]+bofs); }
#pragma unroll
            for (int mt = 0; mt < 2; ++mt)
#pragma unroll
                for (int nt = 0; nt < 4; ++nt) {
                    int blk = nt >> 1, p2 = (nt & 1) * 2;
                    mma16816(acc[mt][nt], ah[mt], bhf[blk][p2], bhf[blk][p2+1]);
                    mma16816(acc[mt][nt], ah[mt], blf[blk][p2], blf[blk][p2+1]);
                    mma16816(acc[mt][nt], al[mt], bhf[blk][p2], bhf[blk][p2+1]);
                }
        }
        __syncthreads();
    }
#pragma unroll
    for (int mt = 0; mt < 2; ++mt)
#pragma unroll
        for (int nt = 0; nt < 4; ++nt) {
            int n = n0 + wn*32 + nt*8 + (lane & 3)*2;
            float b0 = bp[n], b1 = bp[n + 1];
#pragma unroll
            for (int half = 0; half < 2; ++half) {
                int m = m0 + wm*32 + mt*16 + (lane >> 2) + half*8;
                size_t o = (size_t)m*CEMB + n;
                *(float2*)&out[o] = make_float2(acc[mt][nt][half*2] + b0,
                                                acc[mt][nt][half*2+1] + b1);
            }
        }
}

// ==================== launch ====================
extern "C" void kernel_launch(void* const* d_in, const int* in_sizes, int n_in,
                              void* d_out, int out_size)
{
    const float* x  = (const float*)d_in[0];
    const float* Wq = (const float*)d_in[1];
    const float* Wk = (const float*)d_in[2];
    const float* Wv = (const float*)d_in[3];
    const float* Wp = (const float*)d_in[4];
    const float* bp = (const float*)d_in[5];
    float* out = (float*)d_out;

    qkv_kernel<<<dim3(BT/128, 48), 256>>>(x, Wq, Wk, Wv);
    scores_kernel<<<dim3(272, BH), 256>>>();
    zreduce_kernel<<<(BH*TSEQ + 255)/256, 256>>>();
    vscale_kernel<<<(BH*TSEQ*DH/4 + 255)/256, 256>>>();
    pv_kernel<<<dim3(16, BH), 256>>>();
    proj_kernel<<<dim3(BT/128, CEMB/64), 256>>>(Wp, bp, out);
}

// round 6
// speedup vs baseline: 3.4131x; 1.4066x over previous
#include <cuda_runtime.h>
#include <cuda_fp16.h>
#include <cstdint>
#include <cstddef>

#define HEADS 16
#define TSEQ  2048
#define CEMB  1024
#define DH    64
#define BATCH 4
#define BH    (BATCH*HEADS)   // 64
#define BT    (BATCH*TSEQ)    // 8192
#define NT2   16              // 128-row t-tiles
#define APAD  40
#define BNPAD 40
#define BTPAD 72

// ---------------- scratch (device globals; allocation-free) ----------------
__device__ __align__(16) __half g_xh [(size_t)BT*CEMB];
__device__ __align__(16) __half g_wh [(size_t)3*HEADS*CEMB*DH];
__device__ __align__(16) __half g_wl [(size_t)3*HEADS*CEMB*DH];
__device__ __align__(16) __half g_wph[(size_t)CEMB*CEMB];
__device__ __align__(16) __half g_wpl[(size_t)CEMB*CEMB];
__device__ __align__(16) __half g_qh [(size_t)BH*TSEQ*DH];
__device__ __align__(16) __half g_kh [(size_t)BH*TSEQ*DH];
__device__ __align__(16) float  g_v  [(size_t)BH*TSEQ*DH];
__device__ __align__(16) __half g_vh [(size_t)BH*TSEQ*DH];
__device__ __align__(16) __half g_vl [(size_t)BH*TSEQ*DH];
__device__ __align__(16) __half g_P  [(size_t)BH*TSEQ*TSEQ];  // 512 MiB
__device__ __align__(16) __half g_yh [(size_t)BT*CEMB];
__device__ __align__(16) __half g_yl [(size_t)BT*CEMB];
__device__ float g_Zpart[(size_t)BH*NT2*TSEQ];
__device__ float g_Z[(size_t)BH*TSEQ];

// ---------------- helpers ----------------
__device__ __forceinline__ uint32_t smem_u32(const void* p) {
    return (uint32_t)__cvta_generic_to_shared(p);
}
__device__ __forceinline__ void split2h(float x, __half& h, __half& l) {
    h = __float2half(x);
    l = __float2half(x - __half2float(h));
}
__device__ __forceinline__ void store_split2h(__half* ph, __half* pl, float x0, float x1) {
    __half h0, l0, h1, l1;
    split2h(x0, h0, l0); split2h(x1, h1, l1);
    __half2 hh; hh.x = h0; hh.y = h1;
    __half2 ll; ll.x = l0; ll.y = l1;
    *(__half2*)ph = hh;
    *(__half2*)pl = ll;
}
__device__ __forceinline__ float fast_exp(float x) {
    x = fmaxf(-60.f, fminf(60.f, x));
    float z = x * 1.4426950408889634f;
    float n = rintf(z);
    float t = (z - n) * 0.6931471805599453f;
    float p = 1.3888889e-3f;
    p = fmaf(p, t, 8.3333333e-3f);
    p = fmaf(p, t, 4.1666667e-2f);
    p = fmaf(p, t, 1.6666667e-1f);
    p = fmaf(p, t, 0.5f);
    p = fmaf(p, t, 1.0f);
    p = fmaf(p, t, 1.0f);
    return p * __int_as_float(((int)n + 127) << 23);
}
__device__ __forceinline__ void ldsm4(uint32_t r[4], uint32_t a) {
    asm volatile("ldmatrix.sync.aligned.m8n8.x4.shared.b16 {%0,%1,%2,%3},[%4];"
                 : "=r"(r[0]), "=r"(r[1]), "=r"(r[2]), "=r"(r[3]) : "r"(a));
}
__device__ __forceinline__ void ldsm4t(uint32_t r[4], uint32_t a) {
    asm volatile("ldmatrix.sync.aligned.m8n8.x4.trans.shared.b16 {%0,%1,%2,%3},[%4];"
                 : "=r"(r[0]), "=r"(r[1]), "=r"(r[2]), "=r"(r[3]) : "r"(a));
}
__device__ __forceinline__ void mma16816(float c[4], const uint32_t a[4],
                                         uint32_t b0, uint32_t b1) {
    asm volatile(
        "mma.sync.aligned.m16n8k16.row.col.f32.f16.f16.f32 "
        "{%0,%1,%2,%3},{%4,%5,%6,%7},{%8,%9},{%0,%1,%2,%3};"
        : "+f"(c[0]), "+f"(c[1]), "+f"(c[2]), "+f"(c[3])
        : "r"(a[0]), "r"(a[1]), "r"(a[2]), "r"(a[3]), "r"(b0), "r"(b1));
}
struct FragAddr { uint32_t aH[2], aL[2], bH[2], bL[2]; };

// ==================== prep: x -> fp16 hi plane only ====================
__global__ void splitx_kernel(const float* __restrict__ src, int n4)
{
    int i = blockIdx.x * blockDim.x + threadIdx.x;
    if (i >= n4) return;
    float4 v = ((const float4*)src)[i];
    __half2 a; a.x = __float2half(v.x); a.y = __float2half(v.y);
    __half2 b; b.x = __float2half(v.z); b.y = __float2half(v.w);
    ((__half2*)g_xh)[i * 2]     = a;
    ((__half2*)g_xh)[i * 2 + 1] = b;
}

// ==================== prep: weights -> fp16 hi/lo planes ====================
// sel 0: Wqkv (src is one of Wq/Wk/Wv with ofs), sel 1: Wp
__global__ void splitw_kernel(const float* __restrict__ src, int n4, int sel, int ofs4)
{
    int i = blockIdx.x * blockDim.x + threadIdx.x;
    if (i >= n4) return;
    __half* dh = sel ? g_wph : g_wh;
    __half* dl = sel ? g_wpl : g_wl;
    float4 v = ((const float4*)src)[i];
    __half h0,h1,h2,h3,l0,l1,l2,l3;
    split2h(v.x,h0,l0); split2h(v.y,h1,l1); split2h(v.z,h2,l2); split2h(v.w,h3,l3);
    __half2 ha; ha.x=h0; ha.y=h1; __half2 hb; hb.x=h2; hb.y=h3;
    __half2 la; la.x=l0; la.y=l1; __half2 lb; lb.x=l2; lb.y=l3;
    size_t o = (size_t)(ofs4 + i) * 2;
    ((__half2*)dh)[o] = ha; ((__half2*)dh)[o+1] = hb;
    ((__half2*)dl)[o] = la; ((__half2*)dl)[o+1] = lb;
}

// ==================== K1: QKV projection (2-term: xh*(Wh+Wl)) ====================
// grid(BT/128, 48). C[8192,64] = X[8192,1024] @ W_h[1024,64]. B via ldsm.trans.
__global__ __launch_bounds__(256) void qkv_kernel()
{
    __shared__ alignas(16) __half Ah[128*APAD];
    __shared__ alignas(16) __half Bh[32*BTPAD], Bl[32*BTPAD];
    const int tid = threadIdx.x, w = tid >> 5, lane = tid & 31;
    const int wm = w & 3, wn = w >> 2;
    const int m0 = blockIdx.x * 128;
    const int z = blockIdx.y, which = z >> 4, h = z & 15;
    const __half* Wh = g_wh + (size_t)(which * HEADS + h) * CEMB * DH;
    const __half* Wl = g_wl + (size_t)(which * HEADS + h) * CEMB * DH;

    float acc[2][4][4] = {};
    FragAddr F;
#pragma unroll
    for (int mt = 0; mt < 2; ++mt) {
        int ar = wm*32 + mt*16 + (lane & 15), ak = (lane >> 4) * 8;
        F.aH[mt] = smem_u32(&Ah[ar*APAD + ak]);
    }
#pragma unroll
    for (int blk = 0; blk < 2; ++blk) {  // trans-B: row=k, col=n(d)
        int br = (lane & 15), bc = wn*32 + blk*16 + ((lane & 16) ? 8 : 0);
        F.bH[blk] = smem_u32(&Bh[br*BTPAD + bc]);
        F.bL[blk] = smem_u32(&Bl[br*BTPAD + bc]);
    }

    for (int k0 = 0; k0 < CEMB; k0 += 32) {
        // A: 128x32 halves = 512 float4 -> 2 iters
#pragma unroll
        for (int i = 0; i < 2; ++i) {
            int idx = tid + i*256, r = idx >> 2, c8 = (idx & 3) * 8;
            *(float4*)&Ah[r*APAD + c8] = *(const float4*)&g_xh[(size_t)(m0 + r)*CEMB + k0 + c8];
        }
        // B: 32x64 halves per plane = 256 float4 -> 1 iter each
        {
            int r = tid >> 3, c8 = (tid & 7) * 8;
            *(float4*)&Bh[r*BTPAD + c8] = *(const float4*)&Wh[(size_t)(k0 + r)*DH + c8];
            *(float4*)&Bl[r*BTPAD + c8] = *(const float4*)&Wl[(size_t)(k0 + r)*DH + c8];
        }
        __syncthreads();
#pragma unroll
        for (int k16 = 0; k16 < 2; ++k16) {
            uint32_t aofs = k16 * 32;                // 16 halves * 2B
            uint32_t bofs = k16 * 16 * BTPAD * 2;    // 16 k-rows
            uint32_t ah[2][4], bh[2][4], bl[2][4];
#pragma unroll
            for (int mt = 0; mt < 2; ++mt) ldsm4(ah[mt], F.aH[mt]+aofs);
#pragma unroll
            for (int blk = 0; blk < 2; ++blk) { ldsm4t(bh[blk], F.bH[blk]+bofs); ldsm4t(bl[blk], F.bL[blk]+bofs); }
#pragma unroll
            for (int mt = 0; mt < 2; ++mt)
#pragma unroll
                for (int nt = 0; nt < 4; ++nt) {
                    int blk = nt >> 1, p2 = (nt & 1) * 2;
                    mma16816(acc[mt][nt], ah[mt], bh[blk][p2], bh[blk][p2+1]);
                    mma16816(acc[mt][nt], ah[mt], bl[blk][p2], bl[blk][p2+1]);
                }
        }
        __syncthreads();
    }
#pragma unroll
    for (int mt = 0; mt < 2; ++mt)
#pragma unroll
        for (int nt = 0; nt < 4; ++nt)
#pragma unroll
            for (int half = 0; half < 2; ++half) {
                int m = m0 + wm*32 + mt*16 + (lane >> 2) + half*8;
                int n = wn*32 + nt*8 + (lane & 3)*2;
                int b = m >> 11, t = m & (TSEQ - 1);
                size_t base = (((size_t)(b*HEADS + h))*TSEQ + t)*DH + n;
                float c0 = acc[mt][nt][half*2], c1 = acc[mt][nt][half*2+1];
                if (which == 2) {
                    *(float2*)&g_v[base] = make_float2(c0, c1);
                } else {
                    __half2 p2; p2.x = __float2half(c0); p2.y = __float2half(c1);
                    __half* dst = (which == 0) ? g_qh : g_kh;
                    *(__half2*)&dst[base] = p2;
                }
            }
}

// ==================== K2: scores (single-term qh*kh) -> P + col partials ====
// grid(272, 64). tile 128 t-rows x 64 s-cols, lower-triangular tiles only.
__global__ __launch_bounds__(256) void scores_kernel()
{
    __shared__ alignas(16) __half Ah[128*APAD];
    __shared__ alignas(16) __half Bh[64*BNPAD];
    __shared__ float red[8][32];
    const int tid = threadIdx.x, w = tid >> 5, lane = tid & 31;
    const int wm = w & 3, wn = w >> 2;
    const int bh_ = blockIdx.y;
    int p = blockIdx.x;
    int tt = (int)sqrtf((float)p);
    while (tt*tt + tt > p) --tt;
    while ((tt+1)*(tt+1) + (tt+1) <= p) ++tt;
    const int ss = p - tt*tt - tt;
    const int t0 = tt * 128, s0 = ss * 64;
    const __half* qh = g_qh + (size_t)bh_*TSEQ*DH;
    const __half* kh = g_kh + (size_t)bh_*TSEQ*DH;

    float acc[2][4][4] = {};
    FragAddr F;
#pragma unroll
    for (int mt = 0; mt < 2; ++mt) {
        int ar = wm*32 + mt*16 + (lane & 15), ak = (lane >> 4) * 8;
        F.aH[mt] = smem_u32(&Ah[ar*APAD + ak]);
    }
#pragma unroll
    for (int blk = 0; blk < 2; ++blk) {  // natural B: row=n(s), col=k(d)
        int br = wn*32 + blk*16 + (lane & 7) + ((lane & 16) ? 8 : 0);
        int bk = (lane & 8) ? 8 : 0;
        F.bH[blk] = smem_u32(&Bh[br*BNPAD + bk]);
    }

#pragma unroll
    for (int k0 = 0; k0 < DH; k0 += 32) {
#pragma unroll
        for (int i = 0; i < 2; ++i) {
            int idx = tid + i*256, r = idx >> 2, c8 = (idx & 3) * 8;
            *(float4*)&Ah[r*APAD + c8] = *(const float4*)&qh[(size_t)(t0 + r)*DH + k0 + c8];
        }
        {
            int r = tid >> 2, c8 = (tid & 3) * 8;
            *(float4*)&Bh[r*BNPAD + c8] = *(const float4*)&kh[(size_t)(s0 + r)*DH + k0 + c8];
        }
        __syncthreads();
#pragma unroll
        for (int k16 = 0; k16 < 2; ++k16) {
            uint32_t aofs = k16 * 32, bofs = k16 * 32;
            uint32_t ah[2][4], bhf[2][4];
#pragma unroll
            for (int mt = 0; mt < 2; ++mt) ldsm4(ah[mt], F.aH[mt]+aofs);
#pragma unroll
            for (int blk = 0; blk < 2; ++blk) ldsm4(bhf[blk], F.bH[blk]+bofs);
#pragma unroll
            for (int mt = 0; mt < 2; ++mt)
#pragma unroll
                for (int nt = 0; nt < 4; ++nt) {
                    int blk = nt >> 1, p2 = (nt & 1) * 2;
                    mma16816(acc[mt][nt], ah[mt], bhf[blk][p2], bhf[blk][p2+1]);
                }
        }
        __syncthreads();
    }
    const float scale = 0.03125f;
    float cs[4][2] = {};
    size_t Pbase = (size_t)bh_ * TSEQ * TSEQ;
#pragma unroll
    for (int mt = 0; mt < 2; ++mt)
#pragma unroll
        for (int nt = 0; nt < 4; ++nt)
#pragma unroll
            for (int half = 0; half < 2; ++half) {
                int t = t0 + wm*32 + mt*16 + (lane >> 2) + half*8;
                int s = s0 + wn*32 + nt*8 + (lane & 3)*2;
                float e0 = (s     <= t) ? fast_exp(acc[mt][nt][half*2]   * scale) : 0.f;
                float e1 = (s + 1 <= t) ? fast_exp(acc[mt][nt][half*2+1] * scale) : 0.f;
                cs[nt][0] += e0; cs[nt][1] += e1;
                __half2 p2; p2.x = __float2half(e0); p2.y = __float2half(e1);
                *(__half2*)&g_P[Pbase + (size_t)t*TSEQ + s] = p2;
            }
#pragma unroll
    for (int nt = 0; nt < 4; ++nt)
#pragma unroll
        for (int par = 0; par < 2; ++par) {
            float v = cs[nt][par];
            v += __shfl_xor_sync(0xffffffffu, v, 4);
            v += __shfl_xor_sync(0xffffffffu, v, 8);
            v += __shfl_xor_sync(0xffffffffu, v, 16);
            if (lane < 4) red[w][nt*8 + (lane & 3)*2 + par] = v;
        }
    __syncthreads();
    if (tid < 64) {
        int col = tid, wh = col >> 5;
        float s = red[wh*4+0][col & 31] + red[wh*4+1][col & 31]
                + red[wh*4+2][col & 31] + red[wh*4+3][col & 31];
        g_Zpart[((size_t)bh_*NT2 + tt)*TSEQ + s0 + col] = s;
    }
}

// ==================== K3a: Z reduce (deterministic) ====================
__global__ void zreduce_kernel()
{
    int idx = blockIdx.x * blockDim.x + threadIdx.x;
    if (idx >= BH * TSEQ) return;
    int bh_ = idx >> 11, s = idx & (TSEQ - 1), ttmin = s >> 7;
    float sum = 0.f;
    for (int tt = ttmin; tt < NT2; ++tt)
        sum += g_Zpart[((size_t)bh_*NT2 + tt)*TSEQ + s];
    g_Z[idx] = sum;
}

// ==================== K3b: v/Z -> fp16 hi/lo planes ====================
__global__ void vscale_kernel()
{
    int i4 = blockIdx.x * blockDim.x + threadIdx.x;
    if (i4 >= BH * TSEQ * DH / 4) return;
    float rz = 1.0f / g_Z[i4 >> 4];
    float4 v = ((const float4*)g_v)[i4];
    size_t base = (size_t)i4 * 4;
    store_split2h(&g_vh[base],   &g_vl[base],   v.x * rz, v.y * rz);
    store_split2h(&g_vh[base+2], &g_vl[base+2], v.z * rz, v.w * rz);
}

// ==================== K4: y = P @ (vh+vl)  (2-term) ====================
// grid(16, 64). CTA: 128 t-rows x 64 d; k over s in steps of 32.
__global__ __launch_bounds__(256) void pv_kernel()
{
    __shared__ alignas(16) __half Ah[128*APAD];
    __shared__ alignas(16) __half Bh[32*BTPAD], Bl[32*BTPAD];
    const int tid = threadIdx.x, w = tid >> 5, lane = tid & 31;
    const int wm = w & 3, wn = w >> 2;
    const int tt = 15 - blockIdx.x;
    const int bh_ = blockIdx.y;
    const int t0 = tt * 128;
    const __half* Pp = g_P + (size_t)bh_*TSEQ*TSEQ;
    const __half* vh = g_vh + (size_t)bh_*TSEQ*DH;
    const __half* vl = g_vl + (size_t)bh_*TSEQ*DH;

    float acc[2][4][4] = {};
    FragAddr F;
#pragma unroll
    for (int mt = 0; mt < 2; ++mt) {
        int ar = wm*32 + mt*16 + (lane & 15), ak = (lane >> 4) * 8;
        F.aH[mt] = smem_u32(&Ah[ar*APAD + ak]);
    }
#pragma unroll
    for (int blk = 0; blk < 2; ++blk) {  // trans-B: row=k(s), col=n(d)
        int br = (lane & 15), bc = wn*32 + blk*16 + ((lane & 16) ? 8 : 0);
        F.bH[blk] = smem_u32(&Bh[br*BTPAD + bc]);
        F.bL[blk] = smem_u32(&Bl[br*BTPAD + bc]);
    }

    const int nsteps = 4 * (tt + 1);
    for (int st = 0; st < nsteps; ++st) {
        const int s0 = st * 32;
#pragma unroll
        for (int i = 0; i < 2; ++i) {
            int idx = tid + i*256, r = idx >> 2, c8 = (idx & 3) * 8;
            *(float4*)&Ah[r*APAD + c8] = *(const float4*)&Pp[(size_t)(t0 + r)*TSEQ + s0 + c8];
        }
        {
            int r = tid >> 3, c8 = (tid & 7) * 8;
            *(float4*)&Bh[r*BTPAD + c8] = *(const float4*)&vh[(size_t)(s0 + r)*DH + c8];
            *(float4*)&Bl[r*BTPAD + c8] = *(const float4*)&vl[(size_t)(s0 + r)*DH + c8];
        }
        __syncthreads();
#pragma unroll
        for (int k16 = 0; k16 < 2; ++k16) {
            uint32_t aofs = k16 * 32, bofs = k16 * 16 * BTPAD * 2;
            uint32_t ah[2][4], bhf[2][4], blf[2][4];
#pragma unroll
            for (int mt = 0; mt < 2; ++mt) ldsm4(ah[mt], F.aH[mt]+aofs);
#pragma unroll
            for (int blk = 0; blk < 2; ++blk) { ldsm4t(bhf[blk], F.bH[blk]+bofs); ldsm4t(blf[blk], F.bL[blk]+bofs); }
#pragma unroll
            for (int mt = 0; mt < 2; ++mt)
#pragma unroll
                for (int nt = 0; nt < 4; ++nt) {
                    int blk = nt >> 1, p2 = (nt & 1) * 2;
                    mma16816(acc[mt][nt], ah[mt], bhf[blk][p2], bhf[blk][p2+1]);
                    mma16816(acc[mt][nt], ah[mt], blf[blk][p2], blf[blk][p2+1]);
                }
        }
        __syncthreads();
    }
    const int b = bh_ >> 4, h = bh_ & 15;
#pragma unroll
    for (int mt = 0; mt < 2; ++mt)
#pragma unroll
        for (int nt = 0; nt < 4; ++nt)
#pragma unroll
            for (int half = 0; half < 2; ++half) {
                int t = t0 + wm*32 + mt*16 + (lane >> 2) + half*8;
                int n = wn*32 + nt*8 + (lane & 3)*2;
                size_t o = ((size_t)(b*TSEQ + t))*CEMB + h*DH + n;
                store_split2h(&g_yh[o], &g_yl[o],
                              acc[mt][nt][half*2], acc[mt][nt][half*2+1]);
            }
}

// ==================== K5: out = y @ Wp^T + bp  (3-term) ====================
// grid(BT/128, CEMB/64). B natural: Wp [cout][c], n=cout, k=c.
__global__ __launch_bounds__(256) void proj_kernel(
    const float* __restrict__ bp, float* __restrict__ out)
{
    __shared__ alignas(16) __half Ah[128*APAD], Al[128*APAD];
    __shared__ alignas(16) __half Bh[64*BNPAD], Bl[64*BNPAD];
    const int tid = threadIdx.x, w = tid >> 5, lane = tid & 31;
    const int wm = w & 3, wn = w >> 2;
    const int m0 = blockIdx.x * 128, n0 = blockIdx.y * 64;

    float acc[2][4][4] = {};
    FragAddr F;
#pragma unroll
    for (int mt = 0; mt < 2; ++mt) {
        int ar = wm*32 + mt*16 + (lane & 15), ak = (lane >> 4) * 8;
        F.aH[mt] = smem_u32(&Ah[ar*APAD + ak]);
        F.aL[mt] = smem_u32(&Al[ar*APAD + ak]);
    }
#pragma unroll
    for (int blk = 0; blk < 2; ++blk) {
        int br = wn*32 + blk*16 + (lane & 7) + ((lane & 16) ? 8 : 0);
        int bk = (lane & 8) ? 8 : 0;
        F.bH[blk] = smem_u32(&Bh[br*BNPAD + bk]);
        F.bL[blk] = smem_u32(&Bl[br*BNPAD + bk]);
    }

    for (int k0 = 0; k0 < CEMB; k0 += 32) {
#pragma unroll
        for (int i = 0; i < 2; ++i) {
            int idx = tid + i*256, r = idx >> 2, c8 = (idx & 3) * 8;
            *(float4*)&Ah[r*APAD + c8] = *(const float4*)&g_yh[(size_t)(m0 + r)*CEMB + k0 + c8];
            *(float4*)&Al[r*APAD + c8] = *(const float4*)&g_yl[(size_t)(m0 + r)*CEMB + k0 + c8];
        }
        {
            int r = tid >> 2, c8 = (tid & 3) * 8;
            *(float4*)&Bh[r*BNPAD + c8] = *(const float4*)&g_wph[(size_t)(n0 + r)*CEMB + k0 + c8];
            *(float4*)&Bl[r*BNPAD + c8] = *(const float4*)&g_wpl[(size_t)(n0 + r)*CEMB + k0 + c8];
        }
        __syncthreads();
#pragma unroll
        for (int k16 = 0; k16 < 2; ++k16) {
            uint32_t aofs = k16 * 32, bofs = k16 * 32;
            uint32_t ah[2][4], al[2][4], bhf[2][4], blf[2][4];
#pragma unroll
            for (int mt = 0; mt < 2; ++mt) { ldsm4(ah[mt], F.aH[mt]+aofs); ldsm4(al[mt], F.aL[mt]+aofs); }
#pragma unroll
            for (int blk = 0; blk < 2; ++blk) { ldsm4(bhf[blk], F.bH[blk]+bofs); ldsm4(blf[blk], F.bL[blk]+bofs); }
#pragma unroll
            for (int mt = 0; mt < 2; ++mt)
#pragma unroll
                for (int nt = 0; nt < 4; ++nt) {
                    int blk = nt >> 1, p2 = (nt & 1) * 2;
                    mma16816(acc[mt][nt], ah[mt], bhf[blk][p2], bhf[blk][p2+1]);
                    mma16816(acc[mt][nt], ah[mt], blf[blk][p2], blf[blk][p2+1]);
                    mma16816(acc[mt][nt], al[mt], bhf[blk][p2], bhf[blk][p2+1]);
                }
        }
        __syncthreads();
    }
#pragma unroll
    for (int mt = 0; mt < 2; ++mt)
#pragma unroll
        for (int nt = 0; nt < 4; ++nt) {
            int n = n0 + wn*32 + nt*8 + (lane & 3)*2;
            float b0 = bp[n], b1 = bp[n + 1];
#pragma unroll
            for (int half = 0; half < 2; ++half) {
                int m = m0 + wm*32 + mt*16 + (lane >> 2) + half*8;
                size_t o = (size_t)m*CEMB + n;
                *(float2*)&out[o] = make_float2(acc[mt][nt][half*2] + b0,
                                                acc[mt][nt][half*2+1] + b1);
            }
        }
}

// ==================== launch ====================
extern "C" void kernel_launch(void* const* d_in, const int* in_sizes, int n_in,
                              void* d_out, int out_size)
{
    const float* x  = (const float*)d_in[0];
    const float* Wq = (const float*)d_in[1];
    const float* Wk = (const float*)d_in[2];
    const float* Wv = (const float*)d_in[3];
    const float* Wp = (const float*)d_in[4];
    const float* bp = (const float*)d_in[5];
    float* out = (float*)d_out;

    const int nw4 = HEADS * CEMB * DH / 4;   // one of Wq/Wk/Wv in float4s
    splitx_kernel<<<(BT*CEMB/4 + 255)/256, 256>>>(x, BT*CEMB/4);
    splitw_kernel<<<(nw4 + 255)/256, 256>>>(Wq, nw4, 0, 0);
    splitw_kernel<<<(nw4 + 255)/256, 256>>>(Wk, nw4, 0, nw4);
    splitw_kernel<<<(nw4 + 255)/256, 256>>>(Wv, nw4, 0, 2*nw4);
    splitw_kernel<<<(CEMB*CEMB/4 + 255)/256, 256>>>(Wp, CEMB*CEMB/4, 1, 0);

    qkv_kernel<<<dim3(BT/128, 48), 256>>>();
    scores_kernel<<<dim3(272, BH), 256>>>();
    zreduce_kernel<<<(BH*TSEQ + 255)/256, 256>>>();
    vscale_kernel<<<(BH*TSEQ*DH/4 + 255)/256, 256>>>();
    pv_kernel<<<dim3(16, BH), 256>>>();
    proj_kernel<<<dim3(BT/128, CEMB/64), 256>>>(bp, out);
}

// round 7
// speedup vs baseline: 3.9267x; 1.1505x over previous
#include <cuda_runtime.h>
#include <cuda_fp16.h>
#include <cstdint>
#include <cstddef>

#define HEADS 16
#define TSEQ  2048
#define CEMB  1024
#define DH    64
#define BATCH 4
#define BH    (BATCH*HEADS)   // 64
#define BT    (BATCH*TSEQ)    // 8192
#define NT2   16              // 128-row t-tiles
#define APAD  40
#define BNPAD 40
#define BTPAD 72

// ---------------- scratch (device globals; allocation-free) ----------------
__device__ __align__(16) __half g_xh [(size_t)BT*CEMB];
__device__ __align__(16) __half g_wh [(size_t)3*HEADS*CEMB*DH];
__device__ __align__(16) __half g_wph[(size_t)CEMB*CEMB];
__device__ __align__(16) __half g_qh [(size_t)BH*TSEQ*DH];
__device__ __align__(16) __half g_kh [(size_t)BH*TSEQ*DH];
__device__ __align__(16) float  g_v  [(size_t)BH*TSEQ*DH];
__device__ __align__(16) __half g_vh [(size_t)BH*TSEQ*DH];
__device__ __align__(16) __half g_vl [(size_t)BH*TSEQ*DH];
__device__ __align__(16) __half g_P  [(size_t)BH*TSEQ*TSEQ];  // 512 MiB
__device__ __align__(16) __half g_yh [(size_t)BT*CEMB];
__device__ __align__(16) __half g_yl [(size_t)BT*CEMB];
__device__ float g_Zpart[(size_t)BH*NT2*TSEQ];
__device__ float g_Z[(size_t)BH*TSEQ];

// ---------------- helpers ----------------
__device__ __forceinline__ uint32_t smem_u32(const void* p) {
    return (uint32_t)__cvta_generic_to_shared(p);
}
__device__ __forceinline__ void split2h(float x, __half& h, __half& l) {
    h = __float2half(x);
    l = __float2half(x - __half2float(h));
}
__device__ __forceinline__ void store_split2h(__half* ph, __half* pl, float x0, float x1) {
    __half h0, l0, h1, l1;
    split2h(x0, h0, l0); split2h(x1, h1, l1);
    __half2 hh; hh.x = h0; hh.y = h1;
    __half2 ll; ll.x = l0; ll.y = l1;
    *(__half2*)ph = hh;
    *(__half2*)pl = ll;
}
__device__ __forceinline__ float fast_exp(float x) {
    x = fmaxf(-60.f, fminf(60.f, x));
    float z = x * 1.4426950408889634f;
    float n = rintf(z);
    float t = (z - n) * 0.6931471805599453f;
    float p = 1.3888889e-3f;
    p = fmaf(p, t, 8.3333333e-3f);
    p = fmaf(p, t, 4.1666667e-2f);
    p = fmaf(p, t, 1.6666667e-1f);
    p = fmaf(p, t, 0.5f);
    p = fmaf(p, t, 1.0f);
    p = fmaf(p, t, 1.0f);
    return p * __int_as_float(((int)n + 127) << 23);
}
__device__ __forceinline__ void ldsm4(uint32_t r[4], uint32_t a) {
    asm volatile("ldmatrix.sync.aligned.m8n8.x4.shared.b16 {%0,%1,%2,%3},[%4];"
                 : "=r"(r[0]), "=r"(r[1]), "=r"(r[2]), "=r"(r[3]) : "r"(a));
}
__device__ __forceinline__ void ldsm4t(uint32_t r[4], uint32_t a) {
    asm volatile("ldmatrix.sync.aligned.m8n8.x4.trans.shared.b16 {%0,%1,%2,%3},[%4];"
                 : "=r"(r[0]), "=r"(r[1]), "=r"(r[2]), "=r"(r[3]) : "r"(a));
}
__device__ __forceinline__ void mma16816(float c[4], const uint32_t a[4],
                                         uint32_t b0, uint32_t b1) {
    asm volatile(
        "mma.sync.aligned.m16n8k16.row.col.f32.f16.f16.f32 "
        "{%0,%1,%2,%3},{%4,%5,%6,%7},{%8,%9},{%0,%1,%2,%3};"
        : "+f"(c[0]), "+f"(c[1]), "+f"(c[2]), "+f"(c[3])
        : "r"(a[0]), "r"(a[1]), "r"(a[2]), "r"(a[3]), "r"(b0), "r"(b1));
}
struct FragAddr { uint32_t aH[2], aL[2], bH[2], bL[2]; };

// ==================== prep: fp32 -> fp16 (hi plane only) ====================
// sel 0 -> g_xh, 1 -> g_wh (+ofs4), 2 -> g_wph
__global__ void cvt_kernel(const float* __restrict__ src, int n4, int sel, int ofs4)
{
    int i = blockIdx.x * blockDim.x + threadIdx.x;
    if (i >= n4) return;
    __half* d = (sel == 0) ? g_xh : (sel == 1) ? g_wh : g_wph;
    float4 v = ((const float4*)src)[i];
    __half2 a; a.x = __float2half(v.x); a.y = __float2half(v.y);
    __half2 b; b.x = __float2half(v.z); b.y = __float2half(v.w);
    ((__half2*)d)[(size_t)(ofs4 + i) * 2]     = a;
    ((__half2*)d)[(size_t)(ofs4 + i) * 2 + 1] = b;
}

// ==================== K1: QKV projection (1-term: xh*Wh) ====================
// grid(BT/128, 48). C[8192,64] = X[8192,1024] @ W_h[1024,64]. B via ldsm.trans.
__global__ __launch_bounds__(256) void qkv_kernel()
{
    __shared__ alignas(16) __half Ah[128*APAD];
    __shared__ alignas(16) __half Bh[32*BTPAD];
    const int tid = threadIdx.x, w = tid >> 5, lane = tid & 31;
    const int wm = w & 3, wn = w >> 2;
    const int m0 = blockIdx.x * 128;
    const int z = blockIdx.y, which = z >> 4, h = z & 15;
    const __half* Wh = g_wh + (size_t)(which * HEADS + h) * CEMB * DH;

    float acc[2][4][4] = {};
    FragAddr F;
#pragma unroll
    for (int mt = 0; mt < 2; ++mt) {
        int ar = wm*32 + mt*16 + (lane & 15), ak = (lane >> 4) * 8;
        F.aH[mt] = smem_u32(&Ah[ar*APAD + ak]);
    }
#pragma unroll
    for (int blk = 0; blk < 2; ++blk) {  // trans-B: row=k, col=n(d)
        int br = (lane & 15), bc = wn*32 + blk*16 + ((lane & 16) ? 8 : 0);
        F.bH[blk] = smem_u32(&Bh[br*BTPAD + bc]);
    }

    for (int k0 = 0; k0 < CEMB; k0 += 32) {
        // A: 128x32 halves = 512 float4 -> 2 iters
#pragma unroll
        for (int i = 0; i < 2; ++i) {
            int idx = tid + i*256, r = idx >> 2, c8 = (idx & 3) * 8;
            *(float4*)&Ah[r*APAD + c8] = *(const float4*)&g_xh[(size_t)(m0 + r)*CEMB + k0 + c8];
        }
        // B: 32x64 halves = 256 float4 -> 1 iter
        {
            int r = tid >> 3, c8 = (tid & 7) * 8;
            *(float4*)&Bh[r*BTPAD + c8] = *(const float4*)&Wh[(size_t)(k0 + r)*DH + c8];
        }
        __syncthreads();
#pragma unroll
        for (int k16 = 0; k16 < 2; ++k16) {
            uint32_t aofs = k16 * 32;                // 16 halves * 2B
            uint32_t bofs = k16 * 16 * BTPAD * 2;    // 16 k-rows
            uint32_t ah[2][4], bh[2][4];
#pragma unroll
            for (int mt = 0; mt < 2; ++mt) ldsm4(ah[mt], F.aH[mt]+aofs);
#pragma unroll
            for (int blk = 0; blk < 2; ++blk) ldsm4t(bh[blk], F.bH[blk]+bofs);
#pragma unroll
            for (int mt = 0; mt < 2; ++mt)
#pragma unroll
                for (int nt = 0; nt < 4; ++nt) {
                    int blk = nt >> 1, p2 = (nt & 1) * 2;
                    mma16816(acc[mt][nt], ah[mt], bh[blk][p2], bh[blk][p2+1]);
                }
        }
        __syncthreads();
    }
#pragma unroll
    for (int mt = 0; mt < 2; ++mt)
#pragma unroll
        for (int nt = 0; nt < 4; ++nt)
#pragma unroll
            for (int half = 0; half < 2; ++half) {
                int m = m0 + wm*32 + mt*16 + (lane >> 2) + half*8;
                int n = wn*32 + nt*8 + (lane & 3)*2;
                int b = m >> 11, t = m & (TSEQ - 1);
                size_t base = (((size_t)(b*HEADS + h))*TSEQ + t)*DH + n;
                float c0 = acc[mt][nt][half*2], c1 = acc[mt][nt][half*2+1];
                if (which == 2) {
                    *(float2*)&g_v[base] = make_float2(c0, c1);
                } else {
                    __half2 p2; p2.x = __float2half(c0); p2.y = __float2half(c1);
                    __half* dst = (which == 0) ? g_qh : g_kh;
                    *(__half2*)&dst[base] = p2;
                }
            }
}

// ==================== K2: scores (single-term qh*kh) -> P + col partials ====
// grid(272, 64). tile 128 t-rows x 64 s-cols, lower-triangular tiles only.
__global__ __launch_bounds__(256) void scores_kernel()
{
    __shared__ alignas(16) __half Ah[128*APAD];
    __shared__ alignas(16) __half Bh[64*BNPAD];
    __shared__ float red[8][32];
    const int tid = threadIdx.x, w = tid >> 5, lane = tid & 31;
    const int wm = w & 3, wn = w >> 2;
    const int bh_ = blockIdx.y;
    int p = blockIdx.x;
    int tt = (int)sqrtf((float)p);
    while (tt*tt + tt > p) --tt;
    while ((tt+1)*(tt+1) + (tt+1) <= p) ++tt;
    const int ss = p - tt*tt - tt;
    const int t0 = tt * 128, s0 = ss * 64;
    const __half* qh = g_qh + (size_t)bh_*TSEQ*DH;
    const __half* kh = g_kh + (size_t)bh_*TSEQ*DH;

    float acc[2][4][4] = {};
    FragAddr F;
#pragma unroll
    for (int mt = 0; mt < 2; ++mt) {
        int ar = wm*32 + mt*16 + (lane & 15), ak = (lane >> 4) * 8;
        F.aH[mt] = smem_u32(&Ah[ar*APAD + ak]);
    }
#pragma unroll
    for (int blk = 0; blk < 2; ++blk) {  // natural B: row=n(s), col=k(d)
        int br = wn*32 + blk*16 + (lane & 7) + ((lane & 16) ? 8 : 0);
        int bk = (lane & 8) ? 8 : 0;
        F.bH[blk] = smem_u32(&Bh[br*BNPAD + bk]);
    }

#pragma unroll
    for (int k0 = 0; k0 < DH; k0 += 32) {
#pragma unroll
        for (int i = 0; i < 2; ++i) {
            int idx = tid + i*256, r = idx >> 2, c8 = (idx & 3) * 8;
            *(float4*)&Ah[r*APAD + c8] = *(const float4*)&qh[(size_t)(t0 + r)*DH + k0 + c8];
        }
        {
            int r = tid >> 2, c8 = (tid & 3) * 8;
            *(float4*)&Bh[r*BNPAD + c8] = *(const float4*)&kh[(size_t)(s0 + r)*DH + k0 + c8];
        }
        __syncthreads();
#pragma unroll
        for (int k16 = 0; k16 < 2; ++k16) {
            uint32_t aofs = k16 * 32, bofs = k16 * 32;
            uint32_t ah[2][4], bhf[2][4];
#pragma unroll
            for (int mt = 0; mt < 2; ++mt) ldsm4(ah[mt], F.aH[mt]+aofs);
#pragma unroll
            for (int blk = 0; blk < 2; ++blk) ldsm4(bhf[blk], F.bH[blk]+bofs);
#pragma unroll
            for (int mt = 0; mt < 2; ++mt)
#pragma unroll
                for (int nt = 0; nt < 4; ++nt) {
                    int blk = nt >> 1, p2 = (nt & 1) * 2;
                    mma16816(acc[mt][nt], ah[mt], bhf[blk][p2], bhf[blk][p2+1]);
                }
        }
        __syncthreads();
    }
    const float scale = 0.03125f;
    float cs[4][2] = {};
    size_t Pbase = (size_t)bh_ * TSEQ * TSEQ;
#pragma unroll
    for (int mt = 0; mt < 2; ++mt)
#pragma unroll
        for (int nt = 0; nt < 4; ++nt)
#pragma unroll
            for (int half = 0; half < 2; ++half) {
                int t = t0 + wm*32 + mt*16 + (lane >> 2) + half*8;
                int s = s0 + wn*32 + nt*8 + (lane & 3)*2;
                float e0 = (s     <= t) ? fast_exp(acc[mt][nt][half*2]   * scale) : 0.f;
                float e1 = (s + 1 <= t) ? fast_exp(acc[mt][nt][half*2+1] * scale) : 0.f;
                cs[nt][0] += e0; cs[nt][1] += e1;
                __half2 p2; p2.x = __float2half(e0); p2.y = __float2half(e1);
                *(__half2*)&g_P[Pbase + (size_t)t*TSEQ + s] = p2;
            }
#pragma unroll
    for (int nt = 0; nt < 4; ++nt)
#pragma unroll
        for (int par = 0; par < 2; ++par) {
            float v = cs[nt][par];
            v += __shfl_xor_sync(0xffffffffu, v, 4);
            v += __shfl_xor_sync(0xffffffffu, v, 8);
            v += __shfl_xor_sync(0xffffffffu, v, 16);
            if (lane < 4) red[w][nt*8 + (lane & 3)*2 + par] = v;
        }
    __syncthreads();
    if (tid < 64) {
        int col = tid, wh = col >> 5;
        float s = red[wh*4+0][col & 31] + red[wh*4+1][col & 31]
                + red[wh*4+2][col & 31] + red[wh*4+3][col & 31];
        g_Zpart[((size_t)bh_*NT2 + tt)*TSEQ + s0 + col] = s;
    }
}

// ==================== K3a: Z reduce (deterministic) ====================
__global__ void zreduce_kernel()
{
    int idx = blockIdx.x * blockDim.x + threadIdx.x;
    if (idx >= BH * TSEQ) return;
    int bh_ = idx >> 11, s = idx & (TSEQ - 1), ttmin = s >> 7;
    float sum = 0.f;
    for (int tt = ttmin; tt < NT2; ++tt)
        sum += g_Zpart[((size_t)bh_*NT2 + tt)*TSEQ + s];
    g_Z[idx] = sum;
}

// ==================== K3b: v/Z -> fp16 hi/lo planes ====================
__global__ void vscale_kernel()
{
    int i4 = blockIdx.x * blockDim.x + threadIdx.x;
    if (i4 >= BH * TSEQ * DH / 4) return;
    float rz = 1.0f / g_Z[i4 >> 4];
    float4 v = ((const float4*)g_v)[i4];
    size_t base = (size_t)i4 * 4;
    store_split2h(&g_vh[base],   &g_vl[base],   v.x * rz, v.y * rz);
    store_split2h(&g_vh[base+2], &g_vl[base+2], v.z * rz, v.w * rz);
}

// ==================== K4: y = P @ (vh+vl)  (2-term) ====================
// grid(16, 64). CTA: 128 t-rows x 64 d; k over s in steps of 32.
__global__ __launch_bounds__(256) void pv_kernel()
{
    __shared__ alignas(16) __half Ah[128*APAD];
    __shared__ alignas(16) __half Bh[32*BTPAD], Bl[32*BTPAD];
    const int tid = threadIdx.x, w = tid >> 5, lane = tid & 31;
    const int wm = w & 3, wn = w >> 2;
    const int tt = 15 - blockIdx.x;
    const int bh_ = blockIdx.y;
    const int t0 = tt * 128;
    const __half* Pp = g_P + (size_t)bh_*TSEQ*TSEQ;
    const __half* vh = g_vh + (size_t)bh_*TSEQ*DH;
    const __half* vl = g_vl + (size_t)bh_*TSEQ*DH;

    float acc[2][4][4] = {};
    FragAddr F;
#pragma unroll
    for (int mt = 0; mt < 2; ++mt) {
        int ar = wm*32 + mt*16 + (lane & 15), ak = (lane >> 4) * 8;
        F.aH[mt] = smem_u32(&Ah[ar*APAD + ak]);
    }
#pragma unroll
    for (int blk = 0; blk < 2; ++blk) {  // trans-B: row=k(s), col=n(d)
        int br = (lane & 15), bc = wn*32 + blk*16 + ((lane & 16) ? 8 : 0);
        F.bH[blk] = smem_u32(&Bh[br*BTPAD + bc]);
        F.bL[blk] = smem_u32(&Bl[br*BTPAD + bc]);
    }

    const int nsteps = 4 * (tt + 1);
    for (int st = 0; st < nsteps; ++st) {
        const int s0 = st * 32;
#pragma unroll
        for (int i = 0; i < 2; ++i) {
            int idx = tid + i*256, r = idx >> 2, c8 = (idx & 3) * 8;
            *(float4*)&Ah[r*APAD + c8] = *(const float4*)&Pp[(size_t)(t0 + r)*TSEQ + s0 + c8];
        }
        {
            int r = tid >> 3, c8 = (tid & 7) * 8;
            *(float4*)&Bh[r*BTPAD + c8] = *(const float4*)&vh[(size_t)(s0 + r)*DH + c8];
            *(float4*)&Bl[r*BTPAD + c8] = *(const float4*)&vl[(size_t)(s0 + r)*DH + c8];
        }
        __syncthreads();
#pragma unroll
        for (int k16 = 0; k16 < 2; ++k16) {
            uint32_t aofs = k16 * 32, bofs = k16 * 16 * BTPAD * 2;
            uint32_t ah[2][4], bhf[2][4], blf[2][4];
#pragma unroll
            for (int mt = 0; mt < 2; ++mt) ldsm4(ah[mt], F.aH[mt]+aofs);
#pragma unroll
            for (int blk = 0; blk < 2; ++blk) { ldsm4t(bhf[blk], F.bH[blk]+bofs); ldsm4t(blf[blk], F.bL[blk]+bofs); }
#pragma unroll
            for (int mt = 0; mt < 2; ++mt)
#pragma unroll
                for (int nt = 0; nt < 4; ++nt) {
                    int blk = nt >> 1, p2 = (nt & 1) * 2;
                    mma16816(acc[mt][nt], ah[mt], bhf[blk][p2], bhf[blk][p2+1]);
                    mma16816(acc[mt][nt], ah[mt], blf[blk][p2], blf[blk][p2+1]);
                }
        }
        __syncthreads();
    }
    const int b = bh_ >> 4, h = bh_ & 15;
#pragma unroll
    for (int mt = 0; mt < 2; ++mt)
#pragma unroll
        for (int nt = 0; nt < 4; ++nt)
#pragma unroll
            for (int half = 0; half < 2; ++half) {
                int t = t0 + wm*32 + mt*16 + (lane >> 2) + half*8;
                int n = wn*32 + nt*8 + (lane & 3)*2;
                size_t o = ((size_t)(b*TSEQ + t))*CEMB + h*DH + n;
                store_split2h(&g_yh[o], &g_yl[o],
                              acc[mt][nt][half*2], acc[mt][nt][half*2+1]);
            }
}

// ==================== K5: out = (yh+yl) @ WpH^T + bp  (2-term) ====================
// grid(BT/128, CEMB/64). B natural: Wp [cout][c], n=cout, k=c.
__global__ __launch_bounds__(256) void proj_kernel(
    const float* __restrict__ bp, float* __restrict__ out)
{
    __shared__ alignas(16) __half Ah[128*APAD], Al[128*APAD];
    __shared__ alignas(16) __half Bh[64*BNPAD];
    const int tid = threadIdx.x, w = tid >> 5, lane = tid & 31;
    const int wm = w & 3, wn = w >> 2;
    const int m0 = blockIdx.x * 128, n0 = blockIdx.y * 64;

    float acc[2][4][4] = {};
    FragAddr F;
#pragma unroll
    for (int mt = 0; mt < 2; ++mt) {
        int ar = wm*32 + mt*16 + (lane & 15), ak = (lane >> 4) * 8;
        F.aH[mt] = smem_u32(&Ah[ar*APAD + ak]);
        F.aL[mt] = smem_u32(&Al[ar*APAD + ak]);
    }
#pragma unroll
    for (int blk = 0; blk < 2; ++blk) {
        int br = wn*32 + blk*16 + (lane & 7) + ((lane & 16) ? 8 : 0);
        int bk = (lane & 8) ? 8 : 0;
        F.bH[blk] = smem_u32(&Bh[br*BNPAD + bk]);
    }

    for (int k0 = 0; k0 < CEMB; k0 += 32) {
#pragma unroll
        for (int i = 0; i < 2; ++i) {
            int idx = tid + i*256, r = idx >> 2, c8 = (idx & 3) * 8;
            *(float4*)&Ah[r*APAD + c8] = *(const float4*)&g_yh[(size_t)(m0 + r)*CEMB + k0 + c8];
            *(float4*)&Al[r*APAD + c8] = *(const float4*)&g_yl[(size_t)(m0 + r)*CEMB + k0 + c8];
        }
        {
            int r = tid >> 2, c8 = (tid & 3) * 8;
            *(float4*)&Bh[r*BNPAD + c8] = *(const float4*)&g_wph[(size_t)(n0 + r)*CEMB + k0 + c8];
        }
        __syncthreads();
#pragma unroll
        for (int k16 = 0; k16 < 2; ++k16) {
            uint32_t aofs = k16 * 32, bofs = k16 * 32;
            uint32_t ah[2][4], al[2][4], bhf[2][4];
#pragma unroll
            for (int mt = 0; mt < 2; ++mt) { ldsm4(ah[mt], F.aH[mt]+aofs); ldsm4(al[mt], F.aL[mt]+aofs); }
#pragma unroll
            for (int blk = 0; blk < 2; ++blk) ldsm4(bhf[blk], F.bH[blk]+bofs);
#pragma unroll
            for (int mt = 0; mt < 2; ++mt)
#pragma unroll
                for (int nt = 0; nt < 4; ++nt) {
                    int blk = nt >> 1, p2 = (nt & 1) * 2;
                    mma16816(acc[mt][nt], ah[mt], bhf[blk][p2], bhf[blk][p2+1]);
                    mma16816(acc[mt][nt], al[mt], bhf[blk][p2], bhf[blk][p2+1]);
                }
        }
        __syncthreads();
    }
#pragma unroll
    for (int mt = 0; mt < 2; ++mt)
#pragma unroll
        for (int nt = 0; nt < 4; ++nt) {
            int n = n0 + wn*32 + nt*8 + (lane & 3)*2;
            float b0 = bp[n], b1 = bp[n + 1];
#pragma unroll
            for (int half = 0; half < 2; ++half) {
                int m = m0 + wm*32 + mt*16 + (lane >> 2) + half*8;
                size_t o = (size_t)m*CEMB + n;
                *(float2*)&out[o] = make_float2(acc[mt][nt][half*2] + b0,
                                                acc[mt][nt][half*2+1] + b1);
            }
        }
}

// ==================== launch ====================
extern "C" void kernel_launch(void* const* d_in, const int* in_sizes, int n_in,
                              void* d_out, int out_size)
{
    const float* x  = (const float*)d_in[0];
    const float* Wq = (const float*)d_in[1];
    const float* Wk = (const float*)d_in[2];
    const float* Wv = (const float*)d_in[3];
    const float* Wp = (const float*)d_in[4];
    const float* bp = (const float*)d_in[5];
    float* out = (float*)d_out;

    const int nw4 = HEADS * CEMB * DH / 4;   // one of Wq/Wk/Wv in float4s
    cvt_kernel<<<(BT*CEMB/4 + 255)/256, 256>>>(x, BT*CEMB/4, 0, 0);
    cvt_kernel<<<(nw4 + 255)/256, 256>>>(Wq, nw4, 1, 0);
    cvt_kernel<<<(nw4 + 255)/256, 256>>>(Wk, nw4, 1, nw4);
    cvt_kernel<<<(nw4 + 255)/256, 256>>>(Wv, nw4, 1, 2*nw4);
    cvt_kernel<<<(CEMB*CEMB/4 + 255)/256, 256>>>(Wp, CEMB*CEMB/4, 2, 0);

    qkv_kernel<<<dim3(BT/128, 48), 256>>>();
    scores_kernel<<<dim3(272, BH), 256>>>();
    zreduce_kernel<<<(BH*TSEQ + 255)/256, 256>>>();
    vscale_kernel<<<(BH*TSEQ*DH/4 + 255)/256, 256>>>();
    pv_kernel<<<dim3(16, BH), 256>>>();
    proj_kernel<<<dim3(BT/128, CEMB/64), 256>>>(bp, out);
}

// round 8
// speedup vs baseline: 4.4399x; 1.1307x over previous
#include <cuda_runtime.h>
#include <cuda_fp16.h>
#include <cstdint>
#include <cstddef>

#define HEADS 16
#define TSEQ  2048
#define CEMB  1024
#define DH    64
#define BATCH 4
#define BH    (BATCH*HEADS)   // 64
#define BT    (BATCH*TSEQ)    // 8192
#define NT2   16              // 128-row t-tiles
#define APAD  40
#define BNPAD 40
#define BTPAD 72

// ---------------- scratch (device globals; allocation-free) ----------------
__device__ __align__(16) __half g_xh [(size_t)BT*CEMB];
__device__ __align__(16) __half g_wh [(size_t)3*HEADS*CEMB*DH];
__device__ __align__(16) __half g_wph[(size_t)CEMB*CEMB];
__device__ __align__(16) __half g_qh [(size_t)BH*TSEQ*DH];
__device__ __align__(16) __half g_kh [(size_t)BH*TSEQ*DH];
__device__ __align__(16) float  g_v  [(size_t)BH*TSEQ*DH];
__device__ __align__(16) __half g_vh [(size_t)BH*TSEQ*DH];
__device__ __align__(16) __half g_P  [(size_t)BH*TSEQ*TSEQ];  // 512 MiB
__device__ __align__(16) __half g_yh [(size_t)BT*CEMB];
__device__ float g_Zpart[(size_t)BH*NT2*TSEQ];
__device__ float g_Z[(size_t)BH*TSEQ];

// ---------------- helpers ----------------
__device__ __forceinline__ uint32_t smem_u32(const void* p) {
    return (uint32_t)__cvta_generic_to_shared(p);
}
__device__ __forceinline__ float fast_exp(float x) {
    x = fmaxf(-60.f, fminf(60.f, x));
    float z = x * 1.4426950408889634f;
    float n = rintf(z);
    float t = (z - n) * 0.6931471805599453f;
    float p = 1.3888889e-3f;
    p = fmaf(p, t, 8.3333333e-3f);
    p = fmaf(p, t, 4.1666667e-2f);
    p = fmaf(p, t, 1.6666667e-1f);
    p = fmaf(p, t, 0.5f);
    p = fmaf(p, t, 1.0f);
    p = fmaf(p, t, 1.0f);
    return p * __int_as_float(((int)n + 127) << 23);
}
__device__ __forceinline__ void ldsm4(uint32_t r[4], uint32_t a) {
    asm volatile("ldmatrix.sync.aligned.m8n8.x4.shared.b16 {%0,%1,%2,%3},[%4];"
                 : "=r"(r[0]), "=r"(r[1]), "=r"(r[2]), "=r"(r[3]) : "r"(a));
}
__device__ __forceinline__ void ldsm4t(uint32_t r[4], uint32_t a) {
    asm volatile("ldmatrix.sync.aligned.m8n8.x4.trans.shared.b16 {%0,%1,%2,%3},[%4];"
                 : "=r"(r[0]), "=r"(r[1]), "=r"(r[2]), "=r"(r[3]) : "r"(a));
}
__device__ __forceinline__ void mma16816(float c[4], const uint32_t a[4],
                                         uint32_t b0, uint32_t b1) {
    asm volatile(
        "mma.sync.aligned.m16n8k16.row.col.f32.f16.f16.f32 "
        "{%0,%1,%2,%3},{%4,%5,%6,%7},{%8,%9},{%0,%1,%2,%3};"
        : "+f"(c[0]), "+f"(c[1]), "+f"(c[2]), "+f"(c[3])
        : "r"(a[0]), "r"(a[1]), "r"(a[2]), "r"(a[3]), "r"(b0), "r"(b1));
}
struct FragAddr { uint32_t aH[2], aL[2], bH[2], bL[2]; };

// ==================== prep: fp32 -> fp16 (hi plane only) ====================
// sel 0 -> g_xh, 1 -> g_wh (+ofs4), 2 -> g_wph
__global__ void cvt_kernel(const float* __restrict__ src, int n4, int sel, int ofs4)
{
    int i = blockIdx.x * blockDim.x + threadIdx.x;
    if (i >= n4) return;
    __half* d = (sel == 0) ? g_xh : (sel == 1) ? g_wh : g_wph;
    float4 v = ((const float4*)src)[i];
    __half2 a; a.x = __float2half(v.x); a.y = __float2half(v.y);
    __half2 b; b.x = __float2half(v.z); b.y = __float2half(v.w);
    ((__half2*)d)[(size_t)(ofs4 + i) * 2]     = a;
    ((__half2*)d)[(size_t)(ofs4 + i) * 2 + 1] = b;
}

// ==================== K1: QKV projection (1-term: xh*Wh) ====================
// grid(BT/128, 48). C[8192,64] = X[8192,1024] @ W_h[1024,64]. B via ldsm.trans.
__global__ __launch_bounds__(256) void qkv_kernel()
{
    __shared__ alignas(16) __half Ah[128*APAD];
    __shared__ alignas(16) __half Bh[32*BTPAD];
    const int tid = threadIdx.x, w = tid >> 5, lane = tid & 31;
    const int wm = w & 3, wn = w >> 2;
    const int m0 = blockIdx.x * 128;
    const int z = blockIdx.y, which = z >> 4, h = z & 15;
    const __half* Wh = g_wh + (size_t)(which * HEADS + h) * CEMB * DH;

    float acc[2][4][4] = {};
    FragAddr F;
#pragma unroll
    for (int mt = 0; mt < 2; ++mt) {
        int ar = wm*32 + mt*16 + (lane & 15), ak = (lane >> 4) * 8;
        F.aH[mt] = smem_u32(&Ah[ar*APAD + ak]);
    }
#pragma unroll
    for (int blk = 0; blk < 2; ++blk) {  // trans-B: row=k, col=n(d)
        int br = (lane & 15), bc = wn*32 + blk*16 + ((lane & 16) ? 8 : 0);
        F.bH[blk] = smem_u32(&Bh[br*BTPAD + bc]);
    }

    for (int k0 = 0; k0 < CEMB; k0 += 32) {
#pragma unroll
        for (int i = 0; i < 2; ++i) {
            int idx = tid + i*256, r = idx >> 2, c8 = (idx & 3) * 8;
            *(float4*)&Ah[r*APAD + c8] = *(const float4*)&g_xh[(size_t)(m0 + r)*CEMB + k0 + c8];
        }
        {
            int r = tid >> 3, c8 = (tid & 7) * 8;
            *(float4*)&Bh[r*BTPAD + c8] = *(const float4*)&Wh[(size_t)(k0 + r)*DH + c8];
        }
        __syncthreads();
#pragma unroll
        for (int k16 = 0; k16 < 2; ++k16) {
            uint32_t aofs = k16 * 32;
            uint32_t bofs = k16 * 16 * BTPAD * 2;
            uint32_t ah[2][4], bh[2][4];
#pragma unroll
            for (int mt = 0; mt < 2; ++mt) ldsm4(ah[mt], F.aH[mt]+aofs);
#pragma unroll
            for (int blk = 0; blk < 2; ++blk) ldsm4t(bh[blk], F.bH[blk]+bofs);
#pragma unroll
            for (int mt = 0; mt < 2; ++mt)
#pragma unroll
                for (int nt = 0; nt < 4; ++nt) {
                    int blk = nt >> 1, p2 = (nt & 1) * 2;
                    mma16816(acc[mt][nt], ah[mt], bh[blk][p2], bh[blk][p2+1]);
                }
        }
        __syncthreads();
    }
#pragma unroll
    for (int mt = 0; mt < 2; ++mt)
#pragma unroll
        for (int nt = 0; nt < 4; ++nt)
#pragma unroll
            for (int half = 0; half < 2; ++half) {
                int m = m0 + wm*32 + mt*16 + (lane >> 2) + half*8;
                int n = wn*32 + nt*8 + (lane & 3)*2;
                int b = m >> 11, t = m & (TSEQ - 1);
                size_t base = (((size_t)(b*HEADS + h))*TSEQ + t)*DH + n;
                float c0 = acc[mt][nt][half*2], c1 = acc[mt][nt][half*2+1];
                if (which == 2) {
                    *(float2*)&g_v[base] = make_float2(c0, c1);
                } else {
                    __half2 p2; p2.x = __float2half(c0); p2.y = __float2half(c1);
                    __half* dst = (which == 0) ? g_qh : g_kh;
                    *(__half2*)&dst[base] = p2;
                }
            }
}

// ==================== K2: scores (1-term qh*kh) -> P + col partials ====
// grid(272, 64). tile 128 t-rows x 64 s-cols, lower-triangular tiles only.
__global__ __launch_bounds__(256) void scores_kernel()
{
    __shared__ alignas(16) __half Ah[128*APAD];
    __shared__ alignas(16) __half Bh[64*BNPAD];
    __shared__ float red[8][32];
    const int tid = threadIdx.x, w = tid >> 5, lane = tid & 31;
    const int wm = w & 3, wn = w >> 2;
    const int bh_ = blockIdx.y;
    int p = blockIdx.x;
    int tt = (int)sqrtf((float)p);
    while (tt*tt + tt > p) --tt;
    while ((tt+1)*(tt+1) + (tt+1) <= p) ++tt;
    const int ss = p - tt*tt - tt;
    const int t0 = tt * 128, s0 = ss * 64;
    const __half* qh = g_qh + (size_t)bh_*TSEQ*DH;
    const __half* kh = g_kh + (size_t)bh_*TSEQ*DH;

    float acc[2][4][4] = {};
    FragAddr F;
#pragma unroll
    for (int mt = 0; mt < 2; ++mt) {
        int ar = wm*32 + mt*16 + (lane & 15), ak = (lane >> 4) * 8;
        F.aH[mt] = smem_u32(&Ah[ar*APAD + ak]);
    }
#pragma unroll
    for (int blk = 0; blk < 2; ++blk) {  // natural B: row=n(s), col=k(d)
        int br = wn*32 + blk*16 + (lane & 7) + ((lane & 16) ? 8 : 0);
        int bk = (lane & 8) ? 8 : 0;
        F.bH[blk] = smem_u32(&Bh[br*BNPAD + bk]);
    }

#pragma unroll
    for (int k0 = 0; k0 < DH; k0 += 32) {
#pragma unroll
        for (int i = 0; i < 2; ++i) {
            int idx = tid + i*256, r = idx >> 2, c8 = (idx & 3) * 8;
            *(float4*)&Ah[r*APAD + c8] = *(const float4*)&qh[(size_t)(t0 + r)*DH + k0 + c8];
        }
        {
            int r = tid >> 2, c8 = (tid & 3) * 8;
            *(float4*)&Bh[r*BNPAD + c8] = *(const float4*)&kh[(size_t)(s0 + r)*DH + k0 + c8];
        }
        __syncthreads();
#pragma unroll
        for (int k16 = 0; k16 < 2; ++k16) {
            uint32_t aofs = k16 * 32, bofs = k16 * 32;
            uint32_t ah[2][4], bhf[2][4];
#pragma unroll
            for (int mt = 0; mt < 2; ++mt) ldsm4(ah[mt], F.aH[mt]+aofs);
#pragma unroll
            for (int blk = 0; blk < 2; ++blk) ldsm4(bhf[blk], F.bH[blk]+bofs);
#pragma unroll
            for (int mt = 0; mt < 2; ++mt)
#pragma unroll
                for (int nt = 0; nt < 4; ++nt) {
                    int blk = nt >> 1, p2 = (nt & 1) * 2;
                    mma16816(acc[mt][nt], ah[mt], bhf[blk][p2], bhf[blk][p2+1]);
                }
        }
        __syncthreads();
    }
    const float scale = 0.03125f;
    float cs[4][2] = {};
    size_t Pbase = (size_t)bh_ * TSEQ * TSEQ;
#pragma unroll
    for (int mt = 0; mt < 2; ++mt)
#pragma unroll
        for (int nt = 0; nt < 4; ++nt)
#pragma unroll
            for (int half = 0; half < 2; ++half) {
                int t = t0 + wm*32 + mt*16 + (lane >> 2) + half*8;
                int s = s0 + wn*32 + nt*8 + (lane & 3)*2;
                float e0 = (s     <= t) ? fast_exp(acc[mt][nt][half*2]   * scale) : 0.f;
                float e1 = (s + 1 <= t) ? fast_exp(acc[mt][nt][half*2+1] * scale) : 0.f;
                cs[nt][0] += e0; cs[nt][1] += e1;
                __half2 p2; p2.x = __float2half(e0); p2.y = __float2half(e1);
                *(__half2*)&g_P[Pbase + (size_t)t*TSEQ + s] = p2;
            }
#pragma unroll
    for (int nt = 0; nt < 4; ++nt)
#pragma unroll
        for (int par = 0; par < 2; ++par) {
            float v = cs[nt][par];
            v += __shfl_xor_sync(0xffffffffu, v, 4);
            v += __shfl_xor_sync(0xffffffffu, v, 8);
            v += __shfl_xor_sync(0xffffffffu, v, 16);
            if (lane < 4) red[w][nt*8 + (lane & 3)*2 + par] = v;
        }
    __syncthreads();
    if (tid < 64) {
        int col = tid, wh = col >> 5;
        float s = red[wh*4+0][col & 31] + red[wh*4+1][col & 31]
                + red[wh*4+2][col & 31] + red[wh*4+3][col & 31];
        g_Zpart[((size_t)bh_*NT2 + tt)*TSEQ + s0 + col] = s;
    }
}

// ==================== K3a: Z reduce (deterministic) ====================
__global__ void zreduce_kernel()
{
    int idx = blockIdx.x * blockDim.x + threadIdx.x;
    if (idx >= BH * TSEQ) return;
    int bh_ = idx >> 11, s = idx & (TSEQ - 1), ttmin = s >> 7;
    float sum = 0.f;
    for (int tt = ttmin; tt < NT2; ++tt)
        sum += g_Zpart[((size_t)bh_*NT2 + tt)*TSEQ + s];
    g_Z[idx] = sum;
}

// ==================== K3b: v/Z -> single fp16 plane ====================
__global__ void vscale_kernel()
{
    int i4 = blockIdx.x * blockDim.x + threadIdx.x;
    if (i4 >= BH * TSEQ * DH / 4) return;
    float rz = 1.0f / g_Z[i4 >> 4];
    float4 v = ((const float4*)g_v)[i4];
    __half2 a; a.x = __float2half(v.x * rz); a.y = __float2half(v.y * rz);
    __half2 b; b.x = __float2half(v.z * rz); b.y = __float2half(v.w * rz);
    ((__half2*)g_vh)[i4 * 2]     = a;
    ((__half2*)g_vh)[i4 * 2 + 1] = b;
}

// ==================== K4: y = P @ vh  (1-term) ====================
// grid(16, 64). CTA: 128 t-rows x 64 d; k over s in steps of 32.
__global__ __launch_bounds__(256) void pv_kernel()
{
    __shared__ alignas(16) __half Ah[128*APAD];
    __shared__ alignas(16) __half Bh[32*BTPAD];
    const int tid = threadIdx.x, w = tid >> 5, lane = tid & 31;
    const int wm = w & 3, wn = w >> 2;
    const int tt = 15 - blockIdx.x;
    const int bh_ = blockIdx.y;
    const int t0 = tt * 128;
    const __half* Pp = g_P + (size_t)bh_*TSEQ*TSEQ;
    const __half* vh = g_vh + (size_t)bh_*TSEQ*DH;

    float acc[2][4][4] = {};
    FragAddr F;
#pragma unroll
    for (int mt = 0; mt < 2; ++mt) {
        int ar = wm*32 + mt*16 + (lane & 15), ak = (lane >> 4) * 8;
        F.aH[mt] = smem_u32(&Ah[ar*APAD + ak]);
    }
#pragma unroll
    for (int blk = 0; blk < 2; ++blk) {  // trans-B: row=k(s), col=n(d)
        int br = (lane & 15), bc = wn*32 + blk*16 + ((lane & 16) ? 8 : 0);
        F.bH[blk] = smem_u32(&Bh[br*BTPAD + bc]);
    }

    const int nsteps = 4 * (tt + 1);
    for (int st = 0; st < nsteps; ++st) {
        const int s0 = st * 32;
#pragma unroll
        for (int i = 0; i < 2; ++i) {
            int idx = tid + i*256, r = idx >> 2, c8 = (idx & 3) * 8;
            *(float4*)&Ah[r*APAD + c8] = *(const float4*)&Pp[(size_t)(t0 + r)*TSEQ + s0 + c8];
        }
        {
            int r = tid >> 3, c8 = (tid & 7) * 8;
            *(float4*)&Bh[r*BTPAD + c8] = *(const float4*)&vh[(size_t)(s0 + r)*DH + c8];
        }
        __syncthreads();
#pragma unroll
        for (int k16 = 0; k16 < 2; ++k16) {
            uint32_t aofs = k16 * 32, bofs = k16 * 16 * BTPAD * 2;
            uint32_t ah[2][4], bhf[2][4];
#pragma unroll
            for (int mt = 0; mt < 2; ++mt) ldsm4(ah[mt], F.aH[mt]+aofs);
#pragma unroll
            for (int blk = 0; blk < 2; ++blk) ldsm4t(bhf[blk], F.bH[blk]+bofs);
#pragma unroll
            for (int mt = 0; mt < 2; ++mt)
#pragma unroll
                for (int nt = 0; nt < 4; ++nt) {
                    int blk = nt >> 1, p2 = (nt & 1) * 2;
                    mma16816(acc[mt][nt], ah[mt], bhf[blk][p2], bhf[blk][p2+1]);
                }
        }
        __syncthreads();
    }
    const int b = bh_ >> 4, h = bh_ & 15;
#pragma unroll
    for (int mt = 0; mt < 2; ++mt)
#pragma unroll
        for (int nt = 0; nt < 4; ++nt)
#pragma unroll
            for (int half = 0; half < 2; ++half) {
                int t = t0 + wm*32 + mt*16 + (lane >> 2) + half*8;
                int n = wn*32 + nt*8 + (lane & 3)*2;
                size_t o = ((size_t)(b*TSEQ + t))*CEMB + h*DH + n;
                __half2 p2;
                p2.x = __float2half(acc[mt][nt][half*2]);
                p2.y = __float2half(acc[mt][nt][half*2+1]);
                *(__half2*)&g_yh[o] = p2;
            }
}

// ==================== K5: out = yh @ WpH^T + bp  (1-term) ====================
// grid(BT/128, CEMB/64). B natural: Wp [cout][c], n=cout, k=c.
__global__ __launch_bounds__(256) void proj_kernel(
    const float* __restrict__ bp, float* __restrict__ out)
{
    __shared__ alignas(16) __half Ah[128*APAD];
    __shared__ alignas(16) __half Bh[64*BNPAD];
    const int tid = threadIdx.x, w = tid >> 5, lane = tid & 31;
    const int wm = w & 3, wn = w >> 2;
    const int m0 = blockIdx.x * 128, n0 = blockIdx.y * 64;

    float acc[2][4][4] = {};
    FragAddr F;
#pragma unroll
    for (int mt = 0; mt < 2; ++mt) {
        int ar = wm*32 + mt*16 + (lane & 15), ak = (lane >> 4) * 8;
        F.aH[mt] = smem_u32(&Ah[ar*APAD + ak]);
    }
#pragma unroll
    for (int blk = 0; blk < 2; ++blk) {
        int br = wn*32 + blk*16 + (lane & 7) + ((lane & 16) ? 8 : 0);
        int bk = (lane & 8) ? 8 : 0;
        F.bH[blk] = smem_u32(&Bh[br*BNPAD + bk]);
    }

    for (int k0 = 0; k0 < CEMB; k0 += 32) {
#pragma unroll
        for (int i = 0; i < 2; ++i) {
            int idx = tid + i*256, r = idx >> 2, c8 = (idx & 3) * 8;
            *(float4*)&Ah[r*APAD + c8] = *(const float4*)&g_yh[(size_t)(m0 + r)*CEMB + k0 + c8];
        }
        {
            int r = tid >> 2, c8 = (tid & 3) * 8;
            *(float4*)&Bh[r*BNPAD + c8] = *(const float4*)&g_wph[(size_t)(n0 + r)*CEMB + k0 + c8];
        }
        __syncthreads();
#pragma unroll
        for (int k16 = 0; k16 < 2; ++k16) {
            uint32_t aofs = k16 * 32, bofs = k16 * 32;
            uint32_t ah[2][4], bhf[2][4];
#pragma unroll
            for (int mt = 0; mt < 2; ++mt) ldsm4(ah[mt], F.aH[mt]+aofs);
#pragma unroll
            for (int blk = 0; blk < 2; ++blk) ldsm4(bhf[blk], F.bH[blk]+bofs);
#pragma unroll
            for (int mt = 0; mt < 2; ++mt)
#pragma unroll
                for (int nt = 0; nt < 4; ++nt) {
                    int blk = nt >> 1, p2 = (nt & 1) * 2;
                    mma16816(acc[mt][nt], ah[mt], bhf[blk][p2], bhf[blk][p2+1]);
                }
        }
        __syncthreads();
    }
#pragma unroll
    for (int mt = 0; mt < 2; ++mt)
#pragma unroll
        for (int nt = 0; nt < 4; ++nt) {
            int n = n0 + wn*32 + nt*8 + (lane & 3)*2;
            float b0 = bp[n], b1 = bp[n + 1];
#pragma unroll
            for (int half = 0; half < 2; ++half) {
                int m = m0 + wm*32 + mt*16 + (lane >> 2) + half*8;
                size_t o = (size_t)m*CEMB + n;
                *(float2*)&out[o] = make_float2(acc[mt][nt][half*2] + b0,
                                                acc[mt][nt][half*2+1] + b1);
            }
        }
}

// ==================== launch ====================
extern "C" void kernel_launch(void* const* d_in, const int* in_sizes, int n_in,
                              void* d_out, int out_size)
{
    const float* x  = (const float*)d_in[0];
    const float* Wq = (const float*)d_in[1];
    const float* Wk = (const float*)d_in[2];
    const float* Wv = (const float*)d_in[3];
    const float* Wp = (const float*)d_in[4];
    const float* bp = (const float*)d_in[5];
    float* out = (float*)d_out;

    const int nw4 = HEADS * CEMB * DH / 4;   // one of Wq/Wk/Wv in float4s
    cvt_kernel<<<(BT*CEMB/4 + 255)/256, 256>>>(x, BT*CEMB/4, 0, 0);
    cvt_kernel<<<(nw4 + 255)/256, 256>>>(Wq, nw4, 1, 0);
    cvt_kernel<<<(nw4 + 255)/256, 256>>>(Wk, nw4, 1, nw4);
    cvt_kernel<<<(nw4 + 255)/256, 256>>>(Wv, nw4, 1, 2*nw4);
    cvt_kernel<<<(CEMB*CEMB/4 + 255)/256, 256>>>(Wp, CEMB*CEMB/4, 2, 0);

    qkv_kernel<<<dim3(BT/128, 48), 256>>>();
    scores_kernel<<<dim3(272, BH), 256>>>();
    zreduce_kernel<<<(BH*TSEQ + 255)/256, 256>>>();
    vscale_kernel<<<(BH*TSEQ*DH/4 + 255)/256, 256>>>();
    pv_kernel<<<dim3(16, BH), 256>>>();
    proj_kernel<<<dim3(BT/128, CEMB/64), 256>>>(bp, out);
}

// round 9
// speedup vs baseline: 6.0363x; 1.3596x over previous
#include <cuda_runtime.h>
#include <cuda_fp16.h>
#include <cstdint>
#include <cstddef>

#define HEADS 16
#define TSEQ  2048
#define CEMB  1024
#define DH    64
#define BATCH 4
#define BH    (BATCH*HEADS)   // 64
#define BT    (BATCH*TSEQ)    // 8192
#define NT2   16              // 128-row t-tiles
#define NW4   (HEADS*CEMB*DH/4)

// ---------------- scratch (device globals; allocation-free) ----------------
__device__ __align__(16) __half g_xh [(size_t)BT*CEMB];
__device__ __align__(16) __half g_wh [(size_t)3*HEADS*CEMB*DH];
__device__ __align__(16) __half g_wph[(size_t)CEMB*CEMB];
__device__ __align__(16) __half g_qh [(size_t)BH*TSEQ*DH];
__device__ __align__(16) __half g_kh [(size_t)BH*TSEQ*DH];
__device__ __align__(16) float  g_v  [(size_t)BH*TSEQ*DH];
__device__ __align__(16) __half g_vh [(size_t)BH*TSEQ*DH];
__device__ __align__(16) __half g_P  [(size_t)BH*TSEQ*TSEQ];  // 512 MiB
__device__ __align__(16) __half g_yh [(size_t)BT*CEMB];
__device__ float g_Zpart[(size_t)BH*NT2*TSEQ];
__device__ float g_Z[(size_t)BH*TSEQ];

// ---------------- helpers ----------------
__device__ __forceinline__ uint32_t smem_u32(const void* p) {
    return (uint32_t)__cvta_generic_to_shared(p);
}
__device__ __forceinline__ void cpa16(uint32_t dst, const void* src) {
    asm volatile("cp.async.cg.shared.global [%0], [%1], 16;" :: "r"(dst), "l"(src));
}
#define CP_COMMIT() asm volatile("cp.async.commit_group;" ::: "memory")
#define CP_WAIT1()  asm volatile("cp.async.wait_group 1;" ::: "memory")
#define CP_WAIT0()  asm volatile("cp.async.wait_group 0;" ::: "memory")

__device__ __forceinline__ float fast_exp(float x) {
    x = fmaxf(-60.f, fminf(60.f, x));
    float z = x * 1.4426950408889634f;
    float n = rintf(z);
    float t = (z - n) * 0.6931471805599453f;
    float p = 1.3888889e-3f;
    p = fmaf(p, t, 8.3333333e-3f);
    p = fmaf(p, t, 4.1666667e-2f);
    p = fmaf(p, t, 1.6666667e-1f);
    p = fmaf(p, t, 0.5f);
    p = fmaf(p, t, 1.0f);
    p = fmaf(p, t, 1.0f);
    return p * __int_as_float(((int)n + 127) << 23);
}
__device__ __forceinline__ void ldsm4(uint32_t r[4], uint32_t a) {
    asm volatile("ldmatrix.sync.aligned.m8n8.x4.shared.b16 {%0,%1,%2,%3},[%4];"
                 : "=r"(r[0]), "=r"(r[1]), "=r"(r[2]), "=r"(r[3]) : "r"(a));
}
__device__ __forceinline__ void ldsm4t(uint32_t r[4], uint32_t a) {
    asm volatile("ldmatrix.sync.aligned.m8n8.x4.trans.shared.b16 {%0,%1,%2,%3},[%4];"
                 : "=r"(r[0]), "=r"(r[1]), "=r"(r[2]), "=r"(r[3]) : "r"(a));
}
__device__ __forceinline__ void mma16816(float c[4], const uint32_t a[4],
                                         uint32_t b0, uint32_t b1) {
    asm volatile(
        "mma.sync.aligned.m16n8k16.row.col.f32.f16.f16.f32 "
        "{%0,%1,%2,%3},{%4,%5,%6,%7},{%8,%9},{%0,%1,%2,%3};"
        : "+f"(c[0]), "+f"(c[1]), "+f"(c[2]), "+f"(c[3])
        : "r"(a[0]), "r"(a[1]), "r"(a[2]), "r"(a[3]), "r"(b0), "r"(b1));
}

// ==================== prep kernels ====================
// sel 0 -> g_xh, 2 -> g_wph
__global__ void cvt_kernel(const float* __restrict__ src, int n4, int sel)
{
    int i = blockIdx.x * blockDim.x + threadIdx.x;
    if (i >= n4) return;
    __half* d = (sel == 0) ? g_xh : g_wph;
    float4 v = ((const float4*)src)[i];
    __half2 a; a.x = __float2half(v.x); a.y = __float2half(v.y);
    __half2 b; b.x = __float2half(v.z); b.y = __float2half(v.w);
    ((__half2*)d)[(size_t)i * 2]     = a;
    ((__half2*)d)[(size_t)i * 2 + 1] = b;
}
__global__ void cvtw_kernel(const float* __restrict__ Wq, const float* __restrict__ Wk,
                            const float* __restrict__ Wv)
{
    int i = blockIdx.x * blockDim.x + threadIdx.x;
    if (i >= 3 * NW4) return;
    int which = i / NW4, j = i - which * NW4;
    const float* src = (which == 0) ? Wq : (which == 1) ? Wk : Wv;
    float4 v = ((const float4*)src)[j];
    __half2 a; a.x = __float2half(v.x); a.y = __float2half(v.y);
    __half2 b; b.x = __float2half(v.z); b.y = __float2half(v.w);
    ((__half2*)g_wh)[(size_t)i * 2]     = a;
    ((__half2*)g_wh)[(size_t)i * 2 + 1] = b;
}

// ==================== K1: QKV projection (3-stage cp.async) ====================
// grid(BT/128, 48). k-chunk 32, 32 chunks. A 128x32 pitch40, B trans 32x64 pitch72.
__global__ __launch_bounds__(256) void qkv_kernel()
{
    __shared__ alignas(16) __half A[3][128*40];
    __shared__ alignas(16) __half B[3][32*72];
    const int tid = threadIdx.x, w = tid >> 5, lane = tid & 31;
    const int wm = w & 3, wn = w >> 2;
    const int m0 = blockIdx.x * 128;
    const int z = blockIdx.y, which = z >> 4, h = z & 15;
    const __half* Wh = g_wh + (size_t)(which * HEADS + h) * CEMB * DH;

    float acc[2][4][4] = {};
    uint32_t aB[2], bB[2];
#pragma unroll
    for (int mt = 0; mt < 2; ++mt) {
        int ar = wm*32 + mt*16 + (lane & 15), ak = (lane >> 4) * 8;
        aB[mt] = smem_u32(&A[0][ar*40 + ak]);
    }
#pragma unroll
    for (int blk = 0; blk < 2; ++blk) {  // trans-B: row=k, col=n(d)
        int br = (lane & 15), bc = wn*32 + blk*16 + ((lane & 16) ? 8 : 0);
        bB[blk] = smem_u32(&B[0][br*72 + bc]);
    }
    // loader indices
    const int ar0 = tid >> 2, asg = (tid & 3) * 8;          // A: 2 cps (rows tid>>2, tid>>2+64? no: idx-based)
    const int br0 = tid >> 3, bsg = (tid & 7) * 8;          // B: 1 cp

    auto load_chunk = [&](int c, int stg) {
        const int k0 = c * 32;
#pragma unroll
        for (int i = 0; i < 2; ++i) {
            int idx = tid + i * 256, r = idx >> 2, sg = (idx & 3) * 8;
            cpa16(smem_u32(&A[stg][r*40 + sg]), &g_xh[(size_t)(m0 + r)*CEMB + k0 + sg]);
        }
        cpa16(smem_u32(&B[stg][br0*72 + bsg]), &Wh[(size_t)(k0 + br0)*DH + bsg]);
    };

    load_chunk(0, 0); CP_COMMIT();
    load_chunk(1, 1); CP_COMMIT();
    for (int c = 0; c < 32; ++c) {
        CP_WAIT1();
        __syncthreads();
        if (c + 2 < 32) load_chunk(c + 2, (c + 2) % 3);
        CP_COMMIT();
        const uint32_t aS = (c % 3) * (uint32_t)(128*40*2);
        const uint32_t bS = (c % 3) * (uint32_t)(32*72*2);
#pragma unroll
        for (int k16 = 0; k16 < 2; ++k16) {
            uint32_t ah[2][4], bh[2][4];
#pragma unroll
            for (int mt = 0; mt < 2; ++mt) ldsm4(ah[mt], aB[mt] + aS + k16*32);
#pragma unroll
            for (int blk = 0; blk < 2; ++blk) ldsm4t(bh[blk], bB[blk] + bS + k16*2304);
#pragma unroll
            for (int mt = 0; mt < 2; ++mt)
#pragma unroll
                for (int nt = 0; nt < 4; ++nt) {
                    int blk = nt >> 1, p2 = (nt & 1) * 2;
                    mma16816(acc[mt][nt], ah[mt], bh[blk][p2], bh[blk][p2+1]);
                }
        }
    }
    (void)ar0; (void)asg;
#pragma unroll
    for (int mt = 0; mt < 2; ++mt)
#pragma unroll
        for (int nt = 0; nt < 4; ++nt)
#pragma unroll
            for (int half = 0; half < 2; ++half) {
                int m = m0 + wm*32 + mt*16 + (lane >> 2) + half*8;
                int n = wn*32 + nt*8 + (lane & 3)*2;
                int b = m >> 11, t = m & (TSEQ - 1);
                size_t base = (((size_t)(b*HEADS + h))*TSEQ + t)*DH + n;
                float c0 = acc[mt][nt][half*2], c1 = acc[mt][nt][half*2+1];
                if (which == 2) {
                    *(float2*)&g_v[base] = make_float2(c0, c1);
                } else {
                    __half2 p2; p2.x = __float2half(c0); p2.y = __float2half(c1);
                    __half* dst = (which == 0) ? g_qh : g_kh;
                    *(__half2*)&dst[base] = p2;
                }
            }
}

// ==================== K2: scores (single-shot k=64) -> P + col partials ====
// grid(272, 64). tile 128 t-rows x 64 s-cols, causal tiles only.
__global__ __launch_bounds__(256) void scores_kernel()
{
    __shared__ alignas(16) __half A[128*72];
    __shared__ alignas(16) __half B[64*72];
    __shared__ float red[8][32];
    const int tid = threadIdx.x, w = tid >> 5, lane = tid & 31;
    const int wm = w & 3, wn = w >> 2;
    const int bh_ = blockIdx.y;
    int p = blockIdx.x;
    int tt = (int)sqrtf((float)p);
    while (tt*tt + tt > p) --tt;
    while ((tt+1)*(tt+1) + (tt+1) <= p) ++tt;
    const int ss = p - tt*tt - tt;
    const int t0 = tt * 128, s0 = ss * 64;
    const __half* qh = g_qh + (size_t)bh_*TSEQ*DH;
    const __half* kh = g_kh + (size_t)bh_*TSEQ*DH;

    float acc[2][4][4] = {};
    uint32_t aB[2], bB[2];
#pragma unroll
    for (int mt = 0; mt < 2; ++mt) {
        int ar = wm*32 + mt*16 + (lane & 15), ak = (lane >> 4) * 8;
        aB[mt] = smem_u32(&A[ar*72 + ak]);
    }
#pragma unroll
    for (int blk = 0; blk < 2; ++blk) {  // natural B: row=n(s), col=k(d)
        int br = wn*32 + blk*16 + (lane & 7) + ((lane & 16) ? 8 : 0);
        int bk = (lane & 8) ? 8 : 0;
        bB[blk] = smem_u32(&B[br*72 + bk]);
    }

    // single-shot load of full k=64
#pragma unroll
    for (int i = 0; i < 4; ++i) {
        int idx = tid + i * 256, r = idx >> 3, sg = (idx & 7) * 8;
        cpa16(smem_u32(&A[r*72 + sg]), &qh[(size_t)(t0 + r)*DH + sg]);
    }
#pragma unroll
    for (int i = 0; i < 2; ++i) {
        int idx = tid + i * 256, r = idx >> 3, sg = (idx & 7) * 8;
        cpa16(smem_u32(&B[r*72 + sg]), &kh[(size_t)(s0 + r)*DH + sg]);
    }
    CP_COMMIT(); CP_WAIT0();
    __syncthreads();
#pragma unroll
    for (int k16 = 0; k16 < 4; ++k16) {
        uint32_t ah[2][4], bhf[2][4];
#pragma unroll
        for (int mt = 0; mt < 2; ++mt) ldsm4(ah[mt], aB[mt] + k16*32);
#pragma unroll
        for (int blk = 0; blk < 2; ++blk) ldsm4(bhf[blk], bB[blk] + k16*32);
#pragma unroll
        for (int mt = 0; mt < 2; ++mt)
#pragma unroll
            for (int nt = 0; nt < 4; ++nt) {
                int blk = nt >> 1, p2 = (nt & 1) * 2;
                mma16816(acc[mt][nt], ah[mt], bhf[blk][p2], bhf[blk][p2+1]);
            }
    }

    const float scale = 0.03125f;
    float cs[4][2] = {};
    size_t Pbase = (size_t)bh_ * TSEQ * TSEQ;
#pragma unroll
    for (int mt = 0; mt < 2; ++mt)
#pragma unroll
        for (int nt = 0; nt < 4; ++nt)
#pragma unroll
            for (int half = 0; half < 2; ++half) {
                int t = t0 + wm*32 + mt*16 + (lane >> 2) + half*8;
                int s = s0 + wn*32 + nt*8 + (lane & 3)*2;
                float e0 = (s     <= t) ? fast_exp(acc[mt][nt][half*2]   * scale) : 0.f;
                float e1 = (s + 1 <= t) ? fast_exp(acc[mt][nt][half*2+1] * scale) : 0.f;
                cs[nt][0] += e0; cs[nt][1] += e1;
                __half2 p2; p2.x = __float2half(e0); p2.y = __float2half(e1);
                *(__half2*)&g_P[Pbase + (size_t)t*TSEQ + s] = p2;
            }
#pragma unroll
    for (int nt = 0; nt < 4; ++nt)
#pragma unroll
        for (int par = 0; par < 2; ++par) {
            float v = cs[nt][par];
            v += __shfl_xor_sync(0xffffffffu, v, 4);
            v += __shfl_xor_sync(0xffffffffu, v, 8);
            v += __shfl_xor_sync(0xffffffffu, v, 16);
            if (lane < 4) red[w][nt*8 + (lane & 3)*2 + par] = v;
        }
    __syncthreads();
    if (tid < 64) {
        int col = tid, wh = col >> 5;
        float s = red[wh*4+0][col & 31] + red[wh*4+1][col & 31]
                + red[wh*4+2][col & 31] + red[wh*4+3][col & 31];
        g_Zpart[((size_t)bh_*NT2 + tt)*TSEQ + s0 + col] = s;
    }
}

// ==================== K3a: Z reduce (deterministic) ====================
__global__ void zreduce_kernel()
{
    int idx = blockIdx.x * blockDim.x + threadIdx.x;
    if (idx >= BH * TSEQ) return;
    int bh_ = idx >> 11, s = idx & (TSEQ - 1), ttmin = s >> 7;
    float sum = 0.f;
    for (int tt = ttmin; tt < NT2; ++tt)
        sum += g_Zpart[((size_t)bh_*NT2 + tt)*TSEQ + s];
    g_Z[idx] = sum;
}

// ==================== K3b: v/Z -> single fp16 plane ====================
__global__ void vscale_kernel()
{
    int i4 = blockIdx.x * blockDim.x + threadIdx.x;
    if (i4 >= BH * TSEQ * DH / 4) return;
    float rz = 1.0f / g_Z[i4 >> 4];
    float4 v = ((const float4*)g_v)[i4];
    __half2 a; a.x = __float2half(v.x * rz); a.y = __float2half(v.y * rz);
    __half2 b; b.x = __float2half(v.z * rz); b.y = __float2half(v.w * rz);
    ((__half2*)g_vh)[i4 * 2]     = a;
    ((__half2*)g_vh)[i4 * 2 + 1] = b;
}

// ==================== K4: y = P @ vh  (3-stage cp.async) ====================
// grid(16, 64). 128 t-rows x 64 d; s-chunks of 32, nsteps = 4(tt+1).
__global__ __launch_bounds__(256) void pv_kernel()
{
    __shared__ alignas(16) __half A[3][128*40];
    __shared__ alignas(16) __half B[3][32*72];
    const int tid = threadIdx.x, w = tid >> 5, lane = tid & 31;
    const int wm = w & 3, wn = w >> 2;
    const int tt = 15 - blockIdx.x;
    const int bh_ = blockIdx.y;
    const int t0 = tt * 128;
    const __half* Pp = g_P + (size_t)bh_*TSEQ*TSEQ;
    const __half* vh = g_vh + (size_t)bh_*TSEQ*DH;

    float acc[2][4][4] = {};
    uint32_t aB[2], bB[2];
#pragma unroll
    for (int mt = 0; mt < 2; ++mt) {
        int ar = wm*32 + mt*16 + (lane & 15), ak = (lane >> 4) * 8;
        aB[mt] = smem_u32(&A[0][ar*40 + ak]);
    }
#pragma unroll
    for (int blk = 0; blk < 2; ++blk) {  // trans-B: row=k(s), col=n(d)
        int br = (lane & 15), bc = wn*32 + blk*16 + ((lane & 16) ? 8 : 0);
        bB[blk] = smem_u32(&B[0][br*72 + bc]);
    }
    const int br0 = tid >> 3, bsg = (tid & 7) * 8;

    const int nsteps = 4 * (tt + 1);
    auto load_chunk = [&](int st, int stg) {
        const int s0 = st * 32;
#pragma unroll
        for (int i = 0; i < 2; ++i) {
            int idx = tid + i * 256, r = idx >> 2, sg = (idx & 3) * 8;
            cpa16(smem_u32(&A[stg][r*40 + sg]), &Pp[(size_t)(t0 + r)*TSEQ + s0 + sg]);
        }
        cpa16(smem_u32(&B[stg][br0*72 + bsg]), &vh[(size_t)(s0 + br0)*DH + bsg]);
    };

    load_chunk(0, 0); CP_COMMIT();
    if (nsteps > 1) load_chunk(1, 1);
    CP_COMMIT();
    for (int c = 0; c < nsteps; ++c) {
        CP_WAIT1();
        __syncthreads();
        if (c + 2 < nsteps) load_chunk(c + 2, (c + 2) % 3);
        CP_COMMIT();
        const uint32_t aS = (c % 3) * (uint32_t)(128*40*2);
        const uint32_t bS = (c % 3) * (uint32_t)(32*72*2);
#pragma unroll
        for (int k16 = 0; k16 < 2; ++k16) {
            uint32_t ah[2][4], bhf[2][4];
#pragma unroll
            for (int mt = 0; mt < 2; ++mt) ldsm4(ah[mt], aB[mt] + aS + k16*32);
#pragma unroll
            for (int blk = 0; blk < 2; ++blk) ldsm4t(bhf[blk], bB[blk] + bS + k16*2304);
#pragma unroll
            for (int mt = 0; mt < 2; ++mt)
#pragma unroll
                for (int nt = 0; nt < 4; ++nt) {
                    int blk = nt >> 1, p2 = (nt & 1) * 2;
                    mma16816(acc[mt][nt], ah[mt], bhf[blk][p2], bhf[blk][p2+1]);
                }
        }
    }
    const int b = bh_ >> 4, h = bh_ & 15;
#pragma unroll
    for (int mt = 0; mt < 2; ++mt)
#pragma unroll
        for (int nt = 0; nt < 4; ++nt)
#pragma unroll
            for (int half = 0; half < 2; ++half) {
                int t = t0 + wm*32 + mt*16 + (lane >> 2) + half*8;
                int n = wn*32 + nt*8 + (lane & 3)*2;
                size_t o = ((size_t)(b*TSEQ + t))*CEMB + h*DH + n;
                __half2 p2;
                p2.x = __float2half(acc[mt][nt][half*2]);
                p2.y = __float2half(acc[mt][nt][half*2+1]);
                *(__half2*)&g_yh[o] = p2;
            }
}

// ==================== K5: out = yh @ WpH^T + bp (3-stage cp.async) ==========
// grid(BT/128, CEMB/64). B natural 64n x 32k pitch40.
__global__ __launch_bounds__(256) void proj_kernel(
    const float* __restrict__ bp, float* __restrict__ out)
{
    __shared__ alignas(16) __half A[3][128*40];
    __shared__ alignas(16) __half B[3][64*40];
    const int tid = threadIdx.x, w = tid >> 5, lane = tid & 31;
    const int wm = w & 3, wn = w >> 2;
    const int m0 = blockIdx.x * 128, n0 = blockIdx.y * 64;

    float acc[2][4][4] = {};
    uint32_t aB[2], bB[2];
#pragma unroll
    for (int mt = 0; mt < 2; ++mt) {
        int ar = wm*32 + mt*16 + (lane & 15), ak = (lane >> 4) * 8;
        aB[mt] = smem_u32(&A[0][ar*40 + ak]);
    }
#pragma unroll
    for (int blk = 0; blk < 2; ++blk) {  // natural B: row=n, col=k
        int br = wn*32 + blk*16 + (lane & 7) + ((lane & 16) ? 8 : 0);
        int bk = (lane & 8) ? 8 : 0;
        bB[blk] = smem_u32(&B[0][br*40 + bk]);
    }
    const int br0 = tid >> 2, bsg = (tid & 3) * 8;   // 64 rows x 4 segs

    auto load_chunk = [&](int c, int stg) {
        const int k0 = c * 32;
#pragma unroll
        for (int i = 0; i < 2; ++i) {
            int idx = tid + i * 256, r = idx >> 2, sg = (idx & 3) * 8;
            cpa16(smem_u32(&A[stg][r*40 + sg]), &g_yh[(size_t)(m0 + r)*CEMB + k0 + sg]);
        }
        cpa16(smem_u32(&B[stg][br0*40 + bsg]), &g_wph[(size_t)(n0 + br0)*CEMB + k0 + bsg]);
    };

    load_chunk(0, 0); CP_COMMIT();
    load_chunk(1, 1); CP_COMMIT();
    for (int c = 0; c < 32; ++c) {
        CP_WAIT1();
        __syncthreads();
        if (c + 2 < 32) load_chunk(c + 2, (c + 2) % 3);
        CP_COMMIT();
        const uint32_t aS = (c % 3) * (uint32_t)(128*40*2);
        const uint32_t bS = (c % 3) * (uint32_t)(64*40*2);
#pragma unroll
        for (int k16 = 0; k16 < 2; ++k16) {
            uint32_t ah[2][4], bhf[2][4];
#pragma unroll
            for (int mt = 0; mt < 2; ++mt) ldsm4(ah[mt], aB[mt] + aS + k16*32);
#pragma unroll
            for (int blk = 0; blk < 2; ++blk) ldsm4(bhf[blk], bB[blk] + bS + k16*32);
#pragma unroll
            for (int mt = 0; mt < 2; ++mt)
#pragma unroll
                for (int nt = 0; nt < 4; ++nt) {
                    int blk = nt >> 1, p2 = (nt & 1) * 2;
                    mma16816(acc[mt][nt], ah[mt], bhf[blk][p2], bhf[blk][p2+1]);
                }
        }
    }
#pragma unroll
    for (int mt = 0; mt < 2; ++mt)
#pragma unroll
        for (int nt = 0; nt < 4; ++nt) {
            int n = n0 + wn*32 + nt*8 + (lane & 3)*2;
            float b0 = bp[n], b1 = bp[n + 1];
#pragma unroll
            for (int half = 0; half < 2; ++half) {
                int m = m0 + wm*32 + mt*16 + (lane >> 2) + half*8;
                size_t o = (size_t)m*CEMB + n;
                *(float2*)&out[o] = make_float2(acc[mt][nt][half*2] + b0,
                                                acc[mt][nt][half*2+1] + b1);
            }
        }
}

// ==================== launch ====================
extern "C" void kernel_launch(void* const* d_in, const int* in_sizes, int n_in,
                              void* d_out, int out_size)
{
    const float* x  = (const float*)d_in[0];
    const float* Wq = (const float*)d_in[1];
    const float* Wk = (const float*)d_in[2];
    const float* Wv = (const float*)d_in[3];
    const float* Wp = (const float*)d_in[4];
    const float* bp = (const float*)d_in[5];
    float* out = (float*)d_out;

    cvt_kernel<<<(BT*CEMB/4 + 255)/256, 256>>>(x, BT*CEMB/4, 0);
    cvtw_kernel<<<(3*NW4 + 255)/256, 256>>>(Wq, Wk, Wv);
    cvt_kernel<<<(CEMB*CEMB/4 + 255)/256, 256>>>(Wp, CEMB*CEMB/4, 2);

    qkv_kernel<<<dim3(BT/128, 48), 256>>>();
    scores_kernel<<<dim3(272, BH), 256>>>();
    zreduce_kernel<<<(BH*TSEQ + 255)/256, 256>>>();
    vscale_kernel<<<(BH*TSEQ*DH/4 + 255)/256, 256>>>();
    pv_kernel<<<dim3(16, BH), 256>>>();
    proj_kernel<<<dim3(BT/128, CEMB/64), 256>>>(bp, out);
}